// round 8
// baseline (speedup 1.0000x reference)
#include <cuda_runtime.h>
#include <cuda_bf16.h>
#include <cstdint>

#define B_ 128
#define S_ 512
#define I_ 128
#define H_ 128
#define M_ 8
#define KD_ 16
#define R_ 16
#define O_ 128

// output region offsets (floats), concatenated in reference return order
#define OFF_OUT   ((size_t)0)                 // [B,S,O]      8388608
#define OFF_HID   ((size_t)8388608)           // [S,B,M,H]   67108864
#define OFF_AIN   ((size_t)75497472)          // [S,B,M,H]   67108864
#define OFF_ACOMM ((size_t)142606336)         // [S,B,M,H]   67108864
#define OFF_ARIM  ((size_t)209715200)         // [S,B,M,M]    4194304

__device__ float g_P[(size_t)S_ * B_ * M_ * H_];   // precomputed input_part + biases
__device__ float g_Weff[M_ * I_ * H_];             // W_in @ Wp^T per mechanism

typedef unsigned long long ull;

__device__ __forceinline__ ull ffma2(ull a, ull b, ull c) {
    ull d;
    asm("fma.rn.f32x2 %0, %1, %2, %3;" : "=l"(d) : "l"(a), "l"(b), "l"(c));
    return d;
}
__device__ __forceinline__ ull pack2(float x, float y) {
    ull d; asm("mov.b64 %0, {%1, %2};" : "=l"(d) : "f"(x), "f"(y)); return d;
}
__device__ __forceinline__ float2 unpack2(ull v) {
    float2 r; asm("mov.b64 {%0, %1}, %2;" : "=f"(r.x), "=f"(r.y) : "l"(v)); return r;
}
__device__ __forceinline__ float tanh_fast(float x) {
    float e = __expf(2.0f * x);
    return 1.0f - 2.0f / (e + 1.0f);
}
__device__ __forceinline__ void cp8(void* s, const void* g) {
    unsigned ds = (unsigned)__cvta_generic_to_shared(s);
    asm volatile("cp.async.ca.shared.global [%0], [%1], 8;" :: "r"(ds), "l"(g));
}
__device__ __forceinline__ void pair_bar(int id) {
    asm volatile("bar.sync %0, 64;" :: "r"(id) : "memory");
}

// ---------------------------------------------------------------------------
// k_weff: Weff[m][i][o] = sum_h Win[m][i][h] * Wp[m][o][h].  grid (2,8), 256t
// ---------------------------------------------------------------------------
__global__ void k_weff(const float* __restrict__ Win, const float* __restrict__ Wp) {
    __shared__ float sA[64][36];
    __shared__ float sBt[32][132];
    int m = blockIdx.y;
    int i0 = blockIdx.x * 64;
    int tid = threadIdx.x;
    int ty = tid >> 5, tx = tid & 31;
    int w = tid >> 5, lane = tid & 31;

    float acc[8][4];
#pragma unroll
    for (int a = 0; a < 8; a++)
#pragma unroll
        for (int c = 0; c < 4; c++) acc[a][c] = 0.f;

    const float* A = Win + m * 16384;
    const float* Bm = Wp + m * 16384;

    for (int kc = 0; kc < 128; kc += 32) {
        {
            int row = tid >> 2, cs = (tid & 3) * 8;
            const float* ap = A + (i0 + row) * 128 + kc + cs;
            *(float4*)&sA[row][cs]     = *(const float4*)ap;
            *(float4*)&sA[row][cs + 4] = *(const float4*)(ap + 4);
        }
        {
            int og = lane >> 3, ii0 = (lane & 7) * 4;
#pragma unroll
            for (int it = 0; it < 4; it++) {
                int o = (w << 4) + og + (it << 2);
                float4 v = *(const float4*)(Bm + o * 128 + kc + ii0);
                sBt[ii0 + 0][o] = v.x; sBt[ii0 + 1][o] = v.y;
                sBt[ii0 + 2][o] = v.z; sBt[ii0 + 3][o] = v.w;
            }
        }
        __syncthreads();
#pragma unroll 8
        for (int kk = 0; kk < 32; kk++) {
            float4 wv = *(float4*)&sBt[kk][tx * 4];
#pragma unroll
            for (int rr = 0; rr < 8; rr++) {
                float av = sA[ty * 8 + rr][kk];
                acc[rr][0] += av * wv.x; acc[rr][1] += av * wv.y;
                acc[rr][2] += av * wv.z; acc[rr][3] += av * wv.w;
            }
        }
        __syncthreads();
    }
    float* dst = g_Weff + m * 16384;
#pragma unroll
    for (int rr = 0; rr < 8; rr++) {
        float4 v = make_float4(acc[rr][0], acc[rr][1], acc[rr][2], acc[rr][3]);
        *(float4*)&dst[(i0 + ty * 8 + rr) * 128 + tx * 4] = v;
    }
}

// ---------------------------------------------------------------------------
// k_pre v4: one block = 64 (t,b)-rows, all 8 mechanisms; 32 flattened chunks
// with register-prefetch of the next W tiles across the barrier.
// grid 1024, 256 threads, dynamic smem.
// ---------------------------------------------------------------------------
#define PRE_SMEM ((64 * 132 + 2 * 32 * 132) * 4)

__global__ __launch_bounds__(256) void k_pre(const float* __restrict__ x,
        const float* __restrict__ Win, const float* __restrict__ bp,
        const float* __restrict__ cb, float* __restrict__ ain) {
    extern __shared__ float ps[];
    float (*sX)[132]  = (float(*)[132])ps;                // [64][132]
    float (*sW1)[132] = (float(*)[132])(ps + 64 * 132);   // [32][132]
    float (*sW2)[132] = (float(*)[132])(ps + 96 * 132);   // [32][132]

    int r0 = blockIdx.x * 64;
    int t = r0 >> 7, b0 = r0 & 127;
    int tid = threadIdx.x;
    int ty = tid >> 5, tx = tid & 31;

    // load X tile once: 64 rows x 128
    {
        int row = tid >> 2, c0 = (tid & 3) * 32;
        const float* xp = x + ((size_t)(b0 + row) * 512 + t) * 128 + c0;
#pragma unroll
        for (int j = 0; j < 8; j++)
            *(float4*)&sX[row][c0 + 4 * j] = *(const float4*)(xp + 4 * j);
    }

    int iw = tid >> 3, hw = (tid & 7) * 16;   // W-tile load coords
    float4 rw1[4], rw2[4];
    {
        const float* p1 = Win + iw * 128 + hw;          // m=0, kc=0
        const float* p2 = g_Weff + iw * 128 + hw;
#pragma unroll
        for (int j = 0; j < 4; j++) {
            rw1[j] = *(const float4*)(p1 + 4 * j);
            rw2[j] = *(const float4*)(p2 + 4 * j);
        }
    }

    ull acc1[8][2], acc2[8][2];
#pragma unroll
    for (int a = 0; a < 8; a++) {
        acc1[a][0] = 0; acc1[a][1] = 0; acc2[a][0] = 0; acc2[a][1] = 0;
    }
    __syncthreads();   // X tile ready

    for (int cc = 0; cc < 32; cc++) {
        int m = cc >> 2, kc = (cc & 3) * 32;
#pragma unroll
        for (int j = 0; j < 4; j++) {
            *(float4*)&sW1[iw][hw + 4 * j] = rw1[j];
            *(float4*)&sW2[iw][hw + 4 * j] = rw2[j];
        }
        __syncthreads();
        if (cc + 1 < 32) {
            int m2 = (cc + 1) >> 2, kc2 = ((cc + 1) & 3) * 32;
            const float* p1 = Win + m2 * 16384 + (kc2 + iw) * 128 + hw;
            const float* p2 = g_Weff + m2 * 16384 + (kc2 + iw) * 128 + hw;
#pragma unroll
            for (int j = 0; j < 4; j++) {
                rw1[j] = *(const float4*)(p1 + 4 * j);
                rw2[j] = *(const float4*)(p2 + 4 * j);
            }
        }
#pragma unroll 8
        for (int kk = 0; kk < 32; kk++) {
            ulonglong2 w1 = *(const ulonglong2*)&sW1[kk][tx * 4];
            ulonglong2 w2 = *(const ulonglong2*)&sW2[kk][tx * 4];
#pragma unroll
            for (int rr = 0; rr < 8; rr++) {
                float xv = sX[ty * 8 + rr][kc + kk];
                ull xp2 = pack2(xv, xv);
                acc1[rr][0] = ffma2(xp2, w1.x, acc1[rr][0]);
                acc1[rr][1] = ffma2(xp2, w1.y, acc1[rr][1]);
                acc2[rr][0] = ffma2(xp2, w2.x, acc2[rr][0]);
                acc2[rr][1] = ffma2(xp2, w2.y, acc2[rr][1]);
            }
        }
        __syncthreads();
        if ((cc & 3) == 3) {
            float4 bi = *(const float4*)&bp[m * 128 + tx * 4];
            float4 ci = *(const float4*)&cb[m * 128 + tx * 4];
            float4 bias = make_float4(bi.x + ci.x, bi.y + ci.y,
                                      bi.z + ci.z, bi.w + ci.w);
#pragma unroll
            for (int rr = 0; rr < 8; rr++) {
                size_t gr = r0 + ty * 8 + rr;
                size_t base = (gr * 8 + m) * 128 + tx * 4;
                float2 a0 = unpack2(acc1[rr][0]), a1 = unpack2(acc1[rr][1]);
                float2 p0 = unpack2(acc2[rr][0]), p1 = unpack2(acc2[rr][1]);
                *(float4*)&ain[base] = make_float4(a0.x, a0.y, a1.x, a1.y);
                *(float4*)&g_P[base] = make_float4(p0.x + bias.x, p0.y + bias.y,
                                                   p1.x + bias.z, p1.y + bias.w);
                acc1[rr][0] = 0; acc1[rr][1] = 0;
                acc2[rr][0] = 0; acc2[rr][1] = 0;
            }
        }
    }
}

// ---------------------------------------------------------------------------
// k_rnn v4: 128 blocks, 512 threads (16 warps; warp pair per mechanism).
//  - phase A split by h-quarters (pair barrier combines partials)
//  - phase B split by K/Q column group, K halved per lane + shfl combine
//  - phase C split by h-half; state writes warp-private -> __syncwarp back edge
//  - per-thread 8B cp.async P ring (4 deep)
// ---------------------------------------------------------------------------
struct Smem4 {
    float4 Upk[16][8][32];        // 64KB: Upk[w][i][lane] = U[m][32*hq+4i+j][r]
    float V[M_][R_][H_];          // 64KB
    float diag[M_][H_];           // 4 KB
    float Hst[M_][H_];            // 4 KB
    float Hin[M_][H_];            // 4 KB
    float VcT[2][M_][H_];         // 8 KB (parity)
    float P[4][M_ * H_];          // 16 KB ring
    float KQ[2][M_][33];          // parity
    float cpart[M_][2][16];       // phase-A cross-warp partials
};

__global__ __launch_bounds__(512) void k_rnn(
        const float* __restrict__ U, const float* __restrict__ V,
        const float* __restrict__ WQ, const float* __restrict__ WK,
        const float* __restrict__ WV,
        float* __restrict__ hid, float* __restrict__ acomm,
        float* __restrict__ arim) {
    extern __shared__ char raw[];
    Smem4& sm = *reinterpret_cast<Smem4*>(raw);
    int tid = threadIdx.x;
    int b = blockIdx.x;
    int w = tid >> 5, lane = tid & 31;
    const int m = w >> 1, s = w & 1;
    const int r = lane & 15, lq = lane >> 4;
    const int hq = 2 * s + lq;              // phase A quarter
    const int cl = lane & 15, kh = lane >> 4; // phase B col-local / K-half
    const int h0 = 64 * s + 2 * lane;       // phase A2/C h pair

    // -------- init --------
    // U repack: Upk[w][i][lane] = U[m][32*hq + 4i + j][r], j=0..3
    {
#pragma unroll
        for (int i = 0; i < 8; i++) {
            int hb = hq * 32 + i * 4;
            float4 v;
            v.x = U[((size_t)m * 128 + hb + 0) * 16 + r];
            v.y = U[((size_t)m * 128 + hb + 1) * 16 + r];
            v.z = U[((size_t)m * 128 + hb + 2) * 16 + r];
            v.w = U[((size_t)m * 128 + hb + 3) * 16 + r];
            sm.Upk[w][i][lane] = v;
        }
    }
    for (int i = tid * 4; i < M_ * R_ * H_; i += 512 * 4)
        *(float4*)((float*)sm.V + i) = *(const float4*)(V + i);
    for (int e = tid; e < M_ * H_; e += 512) {
        int mm = e >> 7, h = e & 127;
        sm.diag[mm][h] = WV[((size_t)mm * H_ + h) * H_ + h];
        sm.Hst[mm][h] = 0.f;
    }
    // register projection column: s=0 -> W_K col cl (K), s=1 -> W_Q col cl (Q);
    // lane K-half kh; 32 packed f32x2 entries = 64 regs
    ull wreg[32];
    {
        const float* src = (s == 0) ? (WK + m * H_ * KD_ + cl)
                                    : (WQ + m * H_ * KD_ + cl);
#pragma unroll
        for (int i = 0; i < 16; i++) {
            int h = kh * 64 + i * 4;
            wreg[2 * i]     = pack2(src[(h + 0) * KD_], src[(h + 1) * KD_]);
            wreg[2 * i + 1] = pack2(src[(h + 2) * KD_], src[(h + 3) * KD_]);
        }
    }
    const float* Pb = g_P + (size_t)b * 1024;
    // prologue: each thread prefetches its own 8B for t = 0,1,2
#pragma unroll
    for (int pt = 0; pt < 3; pt++) {
        cp8(&sm.P[pt][tid * 2], Pb + (size_t)pt * (B_ * 1024) + tid * 2);
        asm volatile("cp.async.commit_group;");
    }
    __syncthreads();

    for (int t = 0; t < S_; t++) {
        const int p = t & 1;
        if (t + 3 < S_)
            cp8(&sm.P[(t + 3) & 3][tid * 2],
                Pb + (size_t)(t + 3) * (B_ * 1024) + tid * 2);
        asm volatile("cp.async.commit_group;");
        asm volatile("cp.async.wait_group 3;");

        // ---- A1: c_s[r] = sum_{h in warp half} Hst[m][h] * U[m][h][r]
        {
            const float4* Hc = (const float4*)&sm.Hst[m][hq * 32];
            ull s0 = 0, s1 = 0;
#pragma unroll
            for (int i = 0; i < 8; i++) {
                float4 u = sm.Upk[w][i][lane];
                float4 h = Hc[i];
                s0 = ffma2(pack2(h.x, h.y), pack2(u.x, u.y), s0);
                s1 = ffma2(pack2(h.z, h.w), pack2(u.z, u.w), s1);
            }
            float2 t0 = unpack2(s0), t1 = unpack2(s1);
            float partial = (t0.x + t0.y) + (t1.x + t1.y);
            partial += __shfl_xor_sync(0xffffffffu, partial, 16);
            if (lq == 0) sm.cpart[m][s][r] = partial;
        }
        pair_bar(m + 1);

        // ---- A2: rec[h0,h0+1] = sum_r c[r] * V[m][r][h]; Hin = tanh(P+rec)
        float2 hin2;
        {
            ull accA = 0, accB = 0;
#pragma unroll
            for (int rr = 0; rr < 16; rr += 2) {
                float ca = sm.cpart[m][0][rr]     + sm.cpart[m][1][rr];
                float cb2 = sm.cpart[m][0][rr + 1] + sm.cpart[m][1][rr + 1];
                accA = ffma2(pack2(ca, ca),
                             *(const ull*)&sm.V[m][rr][h0], accA);
                accB = ffma2(pack2(cb2, cb2),
                             *(const ull*)&sm.V[m][rr + 1][h0], accB);
            }
            float2 ra = unpack2(accA), rb = unpack2(accB);
            float2 pv = *(const float2*)&sm.P[t & 3][tid * 2];
            hin2.x = tanh_fast(pv.x + ra.x + rb.x);
            hin2.y = tanh_fast(pv.y + ra.y + rb.y);
            *(float2*)&sm.Hin[m][h0] = hin2;
            float2 dg = *(const float2*)&sm.diag[m][h0];
            *(float2*)&sm.VcT[p][m][h0] = make_float2(hin2.x * dg.x, hin2.y * dg.y);
        }
        pair_bar(m + 1);

        // ---- B: proj column 16s+cl, K-half kh, shfl combine
        {
            ull a0 = 0, a1 = 0;
            const ulonglong2* hb = (const ulonglong2*)&sm.Hin[m][64 * kh];
#pragma unroll
            for (int i = 0; i < 16; i++) {
                ulonglong2 h = hb[i];
                a0 = ffma2(h.x, wreg[2 * i], a0);
                a1 = ffma2(h.y, wreg[2 * i + 1], a1);
            }
            float2 s0 = unpack2(a0), s1 = unpack2(a1);
            float d = (s0.x + s0.y) + (s1.x + s1.y);
            d += __shfl_xor_sync(0xffffffffu, d, 16);
            if (kh == 0) sm.KQ[p][m][16 * s + cl] = d;
        }
        __syncthreads();

        // ---- C: redundant 8x8 softmax per warp + comm over own h-half
        {
            int mq = lane >> 2, g = lane & 3;   // lane owns attn[mq][2g],[2g+1]
            float L0 = 0.f, L1 = 0.f;
#pragma unroll
            for (int k = 0; k < 16; k++) {
                float q = sm.KQ[p][mq][16 + k];
                L0 += q * sm.KQ[p][2 * g][k];
                L1 += q * sm.KQ[p][2 * g + 1][k];
            }
            L0 *= 0.25f; L1 *= 0.25f;
            float mx = fmaxf(L0, L1);
            mx = fmaxf(mx, __shfl_xor_sync(0xffffffffu, mx, 1));
            mx = fmaxf(mx, __shfl_xor_sync(0xffffffffu, mx, 2));
            float e0 = __expf(L0 - mx), e1 = __expf(L1 - mx);
            float sum = e0 + e1;
            sum += __shfl_xor_sync(0xffffffffu, sum, 1);
            sum += __shfl_xor_sync(0xffffffffu, sum, 2);
            float inv = 1.0f / sum;
            float a0 = e0 * inv, a1 = e1 * inv;

            if (w == 0)
                *(float2*)&arim[((size_t)t * B_ + b) * 64 + lane * 2] =
                    make_float2(a0, a1);

            // A_comm[m][h0..] = sum_mm attn[mm][m] * VcT[mm][h0..]
            float av = (m & 1) ? a1 : a0;
            ull cx = 0;
#pragma unroll
            for (int mm = 0; mm < 8; mm++) {
                float a = __shfl_sync(0xffffffffu, av, mm * 4 + (m >> 1));
                cx = ffma2(pack2(a, a), *(const ull*)&sm.VcT[p][mm][h0], cx);
            }
            float2 ac = unpack2(cx);
            float2 hn = make_float2(hin2.x + ac.x, hin2.y + ac.y);
            *(float2*)&sm.Hst[m][h0] = hn;
            size_t base = (((size_t)t * B_ + b) * M_ + m) * H_ + h0;
            *(float2*)&hid[base] = hn;
            *(float2*)&acomm[base] = ac;
        }
        __syncwarp();   // Hst cross-lane (same warp) visibility for next A1
    }
}

// ---------------------------------------------------------------------------
// k_out v3: 128x128 tile, BK=16, register-prefetch double buffering, f32x2.
// grid 512, 256 threads.
// ---------------------------------------------------------------------------
__global__ __launch_bounds__(256) void k_out(const float* __restrict__ hid,
        const float* __restrict__ Wo, const float* __restrict__ bo,
        float* __restrict__ outp) {
    __shared__ float sAT[16][132];   // [k][row]
    __shared__ float sB[16][132];    // [k][o]
    int r0 = blockIdx.x * 128;
    int tid = threadIdx.x;
    int tx = tid & 15, ty = tid >> 4;

    int lrow = tid >> 1;            // 0..127
    int lkq  = (tid & 1) * 8;       // 0 or 8
    const float* aptr = hid + (size_t)(r0 + lrow) * 1024 + lkq;
    const float* bptr = Wo + (size_t)lrow * 1024 + lkq;

    ull acc[8][4];
#pragma unroll
    for (int a = 0; a < 8; a++)
#pragma unroll
        for (int c = 0; c < 4; c++) acc[a][c] = 0ull;

    float4 ra0 = *(const float4*)aptr;
    float4 ra1 = *(const float4*)(aptr + 4);
    float4 rb0 = *(const float4*)bptr;
    float4 rb1 = *(const float4*)(bptr + 4);

    for (int kc = 0; kc < 1024; kc += 16) {
        sAT[lkq + 0][lrow] = ra0.x; sAT[lkq + 1][lrow] = ra0.y;
        sAT[lkq + 2][lrow] = ra0.z; sAT[lkq + 3][lrow] = ra0.w;
        sAT[lkq + 4][lrow] = ra1.x; sAT[lkq + 5][lrow] = ra1.y;
        sAT[lkq + 6][lrow] = ra1.z; sAT[lkq + 7][lrow] = ra1.w;
        sB[lkq + 0][lrow] = rb0.x; sB[lkq + 1][lrow] = rb0.y;
        sB[lkq + 2][lrow] = rb0.z; sB[lkq + 3][lrow] = rb0.w;
        sB[lkq + 4][lrow] = rb1.x; sB[lkq + 5][lrow] = rb1.y;
        sB[lkq + 6][lrow] = rb1.z; sB[lkq + 7][lrow] = rb1.w;
        __syncthreads();
        if (kc + 16 < 1024) {
            aptr += 16; bptr += 16;
            ra0 = *(const float4*)aptr; ra1 = *(const float4*)(aptr + 4);
            rb0 = *(const float4*)bptr; rb1 = *(const float4*)(bptr + 4);
        }
#pragma unroll
        for (int k = 0; k < 16; k++) {
            float4 av0 = *(const float4*)&sAT[k][ty * 8];
            float4 av1 = *(const float4*)&sAT[k][ty * 8 + 4];
            float4 bv0 = *(const float4*)&sB[k][tx * 4];
            float4 bv1 = *(const float4*)&sB[k][64 + tx * 4];
            ull bb0 = pack2(bv0.x, bv0.y), bb1 = pack2(bv0.z, bv0.w);
            ull bb2 = pack2(bv1.x, bv1.y), bb3 = pack2(bv1.z, bv1.w);
            float av[8] = {av0.x, av0.y, av0.z, av0.w, av1.x, av1.y, av1.z, av1.w};
#pragma unroll
            for (int rr = 0; rr < 8; rr++) {
                ull ap = pack2(av[rr], av[rr]);
                acc[rr][0] = ffma2(ap, bb0, acc[rr][0]);
                acc[rr][1] = ffma2(ap, bb1, acc[rr][1]);
                acc[rr][2] = ffma2(ap, bb2, acc[rr][2]);
                acc[rr][3] = ffma2(ap, bb3, acc[rr][3]);
            }
        }
        __syncthreads();
    }
    float4 b4a = *(const float4*)&bo[tx * 4];
    float4 b4b = *(const float4*)&bo[64 + tx * 4];
#pragma unroll
    for (int rr = 0; rr < 8; rr++) {
        int rg = r0 + ty * 8 + rr;
        int t = rg >> 7, b = rg & 127;
        float2 v0 = unpack2(acc[rr][0]), v1 = unpack2(acc[rr][1]);
        float2 v2 = unpack2(acc[rr][2]), v3 = unpack2(acc[rr][3]);
        float* orow = outp + ((size_t)b * 512 + t) * 128;
        *(float4*)&orow[tx * 4] =
            make_float4(v0.x + b4a.x, v0.y + b4a.y, v1.x + b4a.z, v1.y + b4a.w);
        *(float4*)&orow[64 + tx * 4] =
            make_float4(v2.x + b4b.x, v2.y + b4b.y, v3.x + b4b.z, v3.y + b4b.w);
    }
}

// ---------------------------------------------------------------------------
extern "C" void kernel_launch(void* const* d_in, const int* in_sizes, int n_in,
                              void* d_out, int out_size) {
    const float* x    = (const float*)d_in[0];
    const float* Wp   = (const float*)d_in[1];
    const float* bp   = (const float*)d_in[2];
    const float* U    = (const float*)d_in[3];
    const float* V    = (const float*)d_in[4];
    const float* cb   = (const float*)d_in[5];
    const float* Win  = (const float*)d_in[6];
    const float* WQ   = (const float*)d_in[7];
    const float* WK   = (const float*)d_in[8];
    const float* WV   = (const float*)d_in[9];
    const float* Wo   = (const float*)d_in[10];
    const float* bo   = (const float*)d_in[11];

    float* out = (float*)d_out;
    float* outputs = out + OFF_OUT;
    float* hid     = out + OFF_HID;
    float* ain     = out + OFF_AIN;
    float* acomm   = out + OFF_ACOMM;
    float* arim    = out + OFF_ARIM;

    cudaFuncSetAttribute(k_rnn, cudaFuncAttributeMaxDynamicSharedMemorySize,
                         (int)sizeof(Smem4));
    cudaFuncSetAttribute(k_pre, cudaFuncAttributeMaxDynamicSharedMemorySize,
                         PRE_SMEM);

    k_weff<<<dim3(2, 8), 256>>>(Win, Wp);
    k_pre<<<1024, 256, PRE_SMEM>>>(x, Win, bp, cb, ain);
    k_rnn<<<128, 512, sizeof(Smem4)>>>(U, V, WQ, WK, WV, hid, acomm, arim);
    k_out<<<512, 256>>>(hid, Wo, bo, outputs);
}

// round 10
// speedup vs baseline: 1.0334x; 1.0334x over previous
#include <cuda_runtime.h>
#include <cuda_bf16.h>
#include <cstdint>

#define B_ 128
#define S_ 512
#define I_ 128
#define H_ 128
#define M_ 8
#define KD_ 16
#define R_ 16
#define O_ 128

// output region offsets (floats), concatenated in reference return order
#define OFF_OUT   ((size_t)0)                 // [B,S,O]      8388608
#define OFF_HID   ((size_t)8388608)           // [S,B,M,H]   67108864
#define OFF_AIN   ((size_t)75497472)          // [S,B,M,H]   67108864
#define OFF_ACOMM ((size_t)142606336)         // [S,B,M,H]   67108864
#define OFF_ARIM  ((size_t)209715200)         // [S,B,M,M]    4194304

__device__ float g_P[(size_t)S_ * B_ * M_ * H_];   // precomputed input_part + biases
__device__ float g_Weff[M_ * I_ * H_];             // W_in @ Wp^T per mechanism

typedef unsigned long long ull;

__device__ __forceinline__ ull ffma2(ull a, ull b, ull c) {
    ull d;
    asm("fma.rn.f32x2 %0, %1, %2, %3;" : "=l"(d) : "l"(a), "l"(b), "l"(c));
    return d;
}
__device__ __forceinline__ ull pack2(float x, float y) {
    ull d; asm("mov.b64 %0, {%1, %2};" : "=l"(d) : "f"(x), "f"(y)); return d;
}
__device__ __forceinline__ float2 unpack2(ull v) {
    float2 r; asm("mov.b64 {%0, %1}, %2;" : "=f"(r.x), "=f"(r.y) : "l"(v)); return r;
}
__device__ __forceinline__ float tanh_fast(float x) {
    float e = __expf(2.0f * x);
    return 1.0f - 2.0f / (e + 1.0f);
}
__device__ __forceinline__ void cp16(void* s, const void* g) {
    unsigned ds = (unsigned)__cvta_generic_to_shared(s);
    asm volatile("cp.async.cg.shared.global [%0], [%1], 16;" :: "r"(ds), "l"(g));
}

// ---------------------------------------------------------------------------
// k_weff: Weff[m][i][o] = sum_h Win[m][i][h] * Wp[m][o][h].  grid (2,8), 256t
// ---------------------------------------------------------------------------
__global__ void k_weff(const float* __restrict__ Win, const float* __restrict__ Wp) {
    __shared__ float sA[64][36];
    __shared__ float sBt[32][132];
    int m = blockIdx.y;
    int i0 = blockIdx.x * 64;
    int tid = threadIdx.x;
    int ty = tid >> 5, tx = tid & 31;
    int w = tid >> 5, lane = tid & 31;

    float acc[8][4];
#pragma unroll
    for (int a = 0; a < 8; a++)
#pragma unroll
        for (int c = 0; c < 4; c++) acc[a][c] = 0.f;

    const float* A = Win + m * 16384;
    const float* Bm = Wp + m * 16384;

    for (int kc = 0; kc < 128; kc += 32) {
        {
            int row = tid >> 2, cs = (tid & 3) * 8;
            const float* ap = A + (i0 + row) * 128 + kc + cs;
            *(float4*)&sA[row][cs]     = *(const float4*)ap;
            *(float4*)&sA[row][cs + 4] = *(const float4*)(ap + 4);
        }
        {
            int og = lane >> 3, ii0 = (lane & 7) * 4;
#pragma unroll
            for (int it = 0; it < 4; it++) {
                int o = (w << 4) + og + (it << 2);
                float4 v = *(const float4*)(Bm + o * 128 + kc + ii0);
                sBt[ii0 + 0][o] = v.x; sBt[ii0 + 1][o] = v.y;
                sBt[ii0 + 2][o] = v.z; sBt[ii0 + 3][o] = v.w;
            }
        }
        __syncthreads();
#pragma unroll 8
        for (int kk = 0; kk < 32; kk++) {
            float4 wv = *(float4*)&sBt[kk][tx * 4];
#pragma unroll
            for (int rr = 0; rr < 8; rr++) {
                float av = sA[ty * 8 + rr][kk];
                acc[rr][0] += av * wv.x; acc[rr][1] += av * wv.y;
                acc[rr][2] += av * wv.z; acc[rr][3] += av * wv.w;
            }
        }
        __syncthreads();
    }
    float* dst = g_Weff + m * 16384;
#pragma unroll
    for (int rr = 0; rr < 8; rr++) {
        float4 v = make_float4(acc[rr][0], acc[rr][1], acc[rr][2], acc[rr][3]);
        *(float4*)&dst[(i0 + ty * 8 + rr) * 128 + tx * 4] = v;
    }
}

// ---------------------------------------------------------------------------
// k_pre v5: one block = 64 (t,b)-rows, all 8 mechanisms; 32 flattened chunks
// with cp.async double-buffered W tiles (latency hidden behind FFMA2 loop).
// grid 1024, 256 threads, dynamic smem.
// ---------------------------------------------------------------------------
#define PRE_SMEM ((64 * 132 + 4 * 32 * 132) * 4)

__global__ __launch_bounds__(256) void k_pre(const float* __restrict__ x,
        const float* __restrict__ Win, const float* __restrict__ bp,
        const float* __restrict__ cb, float* __restrict__ ain) {
    extern __shared__ float ps[];
    float (*sX)[132] = (float(*)[132])ps;                      // [64][132]
    // W buffers: buf b at ps + 64*132 + b*(64*132); sW1 then sW2 (each [32][132])
    float* wbase = ps + 64 * 132;

    int r0 = blockIdx.x * 64;
    int t = r0 >> 7, b0 = r0 & 127;
    int tid = threadIdx.x;
    int ty = tid >> 5, tx = tid & 31;

    int iw = tid >> 3, hw = (tid & 7) * 16;   // W-tile copy coords

    // prologue: async-prefetch chunk 0 (m=0, kc=0) into buffer 0
    {
        float* d1 = wbase + iw * 132 + hw;
        float* d2 = wbase + 32 * 132 + iw * 132 + hw;
        const float* p1 = Win + iw * 128 + hw;
        const float* p2 = g_Weff + iw * 128 + hw;
#pragma unroll
        for (int j = 0; j < 4; j++) {
            cp16(d1 + 4 * j, p1 + 4 * j);
            cp16(d2 + 4 * j, p2 + 4 * j);
        }
        asm volatile("cp.async.commit_group;");
    }
    // load X tile once: 64 rows x 128
    {
        int row = tid >> 2, c0 = (tid & 3) * 32;
        const float* xp = x + ((size_t)(b0 + row) * 512 + t) * 128 + c0;
#pragma unroll
        for (int j = 0; j < 8; j++)
            *(float4*)&sX[row][c0 + 4 * j] = *(const float4*)(xp + 4 * j);
    }

    ull acc1[8][2], acc2[8][2];
#pragma unroll
    for (int a = 0; a < 8; a++) {
        acc1[a][0] = 0; acc1[a][1] = 0; acc2[a][0] = 0; acc2[a][1] = 0;
    }
    __syncthreads();   // X ready; compute(-1) done

    for (int cc = 0; cc < 32; cc++) {
        int m = cc >> 2, kc = (cc & 3) * 32;
        // prefetch next chunk into the other buffer (safe: barrier at loop
        // bottom guarantees compute on that buffer finished)
        if (cc + 1 < 32) {
            int m2 = (cc + 1) >> 2, kc2 = ((cc + 1) & 3) * 32;
            float* wb = wbase + ((cc + 1) & 1) * (64 * 132);
            float* d1 = wb + iw * 132 + hw;
            float* d2 = wb + 32 * 132 + iw * 132 + hw;
            const float* p1 = Win + m2 * 16384 + (kc2 + iw) * 128 + hw;
            const float* p2 = g_Weff + m2 * 16384 + (kc2 + iw) * 128 + hw;
#pragma unroll
            for (int j = 0; j < 4; j++) {
                cp16(d1 + 4 * j, p1 + 4 * j);
                cp16(d2 + 4 * j, p2 + 4 * j);
            }
            asm volatile("cp.async.commit_group;");
            asm volatile("cp.async.wait_group 1;");
        } else {
            asm volatile("cp.async.wait_group 0;");
        }
        __syncthreads();   // chunk cc visible to all

        const float* wb = wbase + (cc & 1) * (64 * 132);
        const float* sW1 = wb;
        const float* sW2 = wb + 32 * 132;
#pragma unroll 8
        for (int kk = 0; kk < 32; kk++) {
            ulonglong2 w1 = *(const ulonglong2*)&sW1[kk * 132 + tx * 4];
            ulonglong2 w2 = *(const ulonglong2*)&sW2[kk * 132 + tx * 4];
#pragma unroll
            for (int rr = 0; rr < 8; rr++) {
                float xv = sX[ty * 8 + rr][kc + kk];
                ull xp2 = pack2(xv, xv);
                acc1[rr][0] = ffma2(xp2, w1.x, acc1[rr][0]);
                acc1[rr][1] = ffma2(xp2, w1.y, acc1[rr][1]);
                acc2[rr][0] = ffma2(xp2, w2.x, acc2[rr][0]);
                acc2[rr][1] = ffma2(xp2, w2.y, acc2[rr][1]);
            }
        }
        if ((cc & 3) == 3) {
            float4 bi = *(const float4*)&bp[m * 128 + tx * 4];
            float4 ci = *(const float4*)&cb[m * 128 + tx * 4];
            float4 bias = make_float4(bi.x + ci.x, bi.y + ci.y,
                                      bi.z + ci.z, bi.w + ci.w);
#pragma unroll
            for (int rr = 0; rr < 8; rr++) {
                size_t gr = r0 + ty * 8 + rr;
                size_t base = (gr * 8 + m) * 128 + tx * 4;
                float2 a0 = unpack2(acc1[rr][0]), a1 = unpack2(acc1[rr][1]);
                float2 p0 = unpack2(acc2[rr][0]), p1 = unpack2(acc2[rr][1]);
                *(float4*)&ain[base] = make_float4(a0.x, a0.y, a1.x, a1.y);
                *(float4*)&g_P[base] = make_float4(p0.x + bias.x, p0.y + bias.y,
                                                   p1.x + bias.z, p1.y + bias.w);
                acc1[rr][0] = 0; acc1[rr][1] = 0;
                acc2[rr][0] = 0; acc2[rr][1] = 0;
            }
        }
        __syncthreads();   // compute done -> buffer may be overwritten
    }
}

// ---------------------------------------------------------------------------
// k_rnn v3 (R7, best known) + diag in registers. 128 blocks, 256 threads.
// ---------------------------------------------------------------------------
struct Smem3 {
    float4 Ut4[M_][16][32];       // 65536 B: Ut4[m][i][lane].j = U[m][hf*64+4i+j][r]
    float V[M_][R_][H_];          // 65536 B
    float Hst[M_][H_];            // 4 KB
    float Hin[M_][H_];            // 4 KB
    float VcT[2][M_][H_];         // 8 KB (parity)
    float P[4][M_ * H_];          // 16 KB ring
    float KQ[2][M_][33];          // parity
};

__global__ __launch_bounds__(256) void k_rnn(
        const float* __restrict__ U, const float* __restrict__ V,
        const float* __restrict__ WQ, const float* __restrict__ WK,
        const float* __restrict__ WV,
        float* __restrict__ hid, float* __restrict__ acomm,
        float* __restrict__ arim) {
    extern __shared__ char raw[];
    Smem3& sm = *reinterpret_cast<Smem3*>(raw);
    int tid = threadIdx.x;
    int b = blockIdx.x;
    int w = tid >> 5, lane = tid & 31;
    const int m = w;
    const int r = lane & 15, hf = lane >> 4;

    // -------- init --------
    // U repack: Ut4[m][i][lane].j = U[m][hf*64 + 4i + j][r]
    {
#pragma unroll
        for (int i = 0; i < 16; i++) {
            int hb = hf * 64 + i * 4;
            float4 v;
            v.x = U[((size_t)m * 128 + hb + 0) * 16 + r];
            v.y = U[((size_t)m * 128 + hb + 1) * 16 + r];
            v.z = U[((size_t)m * 128 + hb + 2) * 16 + r];
            v.w = U[((size_t)m * 128 + hb + 3) * 16 + r];
            sm.Ut4[m][i][lane] = v;
        }
    }
    for (int i = tid * 4; i < M_ * R_ * H_; i += 256 * 4)
        *(float4*)((float*)sm.V + i) = *(const float4*)(V + i);
    for (int e = tid; e < M_ * H_; e += 256) {
        int mm = e >> 7, h = e & 127;
        sm.Hst[mm][h] = 0.f;
    }
    // diag of W_V for this lane's 4 h values — registers
    float4 dreg;
    {
        int h = lane * 4;
        dreg.x = WV[((size_t)m * H_ + h + 0) * H_ + h + 0];
        dreg.y = WV[((size_t)m * H_ + h + 1) * H_ + h + 1];
        dreg.z = WV[((size_t)m * H_ + h + 2) * H_ + h + 2];
        dreg.w = WV[((size_t)m * H_ + h + 3) * H_ + h + 3];
    }
    // register-resident projection column: lane c<16 -> W_K col c, c>=16 -> W_Q col c-16
    ull wreg[64];
    {
        const float* src = (lane < 16) ? (WK + m * H_ * KD_ + lane)
                                       : (WQ + m * H_ * KD_ + (lane - 16));
#pragma unroll
        for (int hp = 0; hp < 64; hp++)
            wreg[hp] = pack2(src[(2 * hp) * KD_], src[(2 * hp + 1) * KD_]);
    }
    const float* Pb = g_P + (size_t)b * 1024;
    // prologue: prefetch t = 0,1,2
#pragma unroll
    for (int pt = 0; pt < 3; pt++) {
        cp16(&sm.P[pt][tid * 4], Pb + (size_t)pt * (B_ * 1024) + tid * 4);
        asm volatile("cp.async.commit_group;");
    }
    __syncthreads();

    for (int t = 0; t < S_; t++) {
        const int p = t & 1;
        if (t + 3 < S_)
            cp16(&sm.P[(t + 3) & 3][tid * 4],
                 Pb + (size_t)(t + 3) * (B_ * 1024) + tid * 4);
        asm volatile("cp.async.commit_group;");
        asm volatile("cp.async.wait_group 3;");

        // ---- phase A: rec = (H @ U) @ V ; Hin = tanh(P+rec) ; VcT = Hin*diag
        float4 hin;
        {
            const float4* Hc = (const float4*)&sm.Hst[m][hf * 64];
            ull s0 = 0, s1 = 0;
#pragma unroll
            for (int i = 0; i < 16; i++) {
                float4 u = sm.Ut4[m][i][lane];
                float4 h = Hc[i];
                s0 = ffma2(pack2(h.x, h.y), pack2(u.x, u.y), s0);
                s1 = ffma2(pack2(h.z, h.w), pack2(u.z, u.w), s1);
            }
            float2 t0 = unpack2(s0), t1 = unpack2(s1);
            float partial = (t0.x + t0.y) + (t1.x + t1.y);
            partial += __shfl_xor_sync(0xffffffffu, partial, 16);
            ull ax = 0, ay = 0;
#pragma unroll
            for (int rr = 0; rr < 16; rr++) {
                float tr = __shfl_sync(0xffffffffu, partial, rr);
                ull tp = pack2(tr, tr);
                ulonglong2 v = *(const ulonglong2*)&sm.V[m][rr][lane * 4];
                ax = ffma2(tp, v.x, ax);
                ay = ffma2(tp, v.y, ay);
            }
            float2 a01 = unpack2(ax), a23 = unpack2(ay);
            float4 pv = *(const float4*)&sm.P[t & 3][tid * 4];
            hin.x = tanh_fast(pv.x + a01.x);
            hin.y = tanh_fast(pv.y + a01.y);
            hin.z = tanh_fast(pv.z + a23.x);
            hin.w = tanh_fast(pv.w + a23.y);
            *(float4*)&sm.Hin[m][lane * 4] = hin;
            *(float4*)&sm.VcT[p][m][lane * 4] =
                make_float4(hin.x * dreg.x, hin.y * dreg.y,
                            hin.z * dreg.z, hin.w * dreg.w);
        }
        __syncwarp();

        // ---- phase B: K/Q projection, weights in registers, Hin broadcast
        {
            ull acc0 = 0, acc1 = 0;
            const ulonglong2* hb = (const ulonglong2*)&sm.Hin[m][0];
#pragma unroll
            for (int i = 0; i < 32; i++) {
                ulonglong2 h = hb[i];
                acc0 = ffma2(h.x, wreg[2 * i], acc0);
                acc1 = ffma2(h.y, wreg[2 * i + 1], acc1);
            }
            float2 s0 = unpack2(acc0), s1 = unpack2(acc1);
            sm.KQ[p][m][lane] = (s0.x + s0.y) + (s1.x + s1.y);
        }
        __syncthreads();

        // ---- phase C: per-warp redundant 8x8 attention + comm + update
        {
            int mq = lane >> 2, g = lane & 3;   // lane owns logits[mq][2g],[2g+1]
            float L0 = 0.f, L1 = 0.f;
#pragma unroll
            for (int k = 0; k < 16; k++) {
                float q = sm.KQ[p][mq][16 + k];
                L0 += q * sm.KQ[p][2 * g][k];
                L1 += q * sm.KQ[p][2 * g + 1][k];
            }
            L0 *= 0.25f; L1 *= 0.25f;
            float mx = fmaxf(L0, L1);
            mx = fmaxf(mx, __shfl_xor_sync(0xffffffffu, mx, 1));
            mx = fmaxf(mx, __shfl_xor_sync(0xffffffffu, mx, 2));
            float e0 = __expf(L0 - mx), e1 = __expf(L1 - mx);
            float s = e0 + e1;
            s += __shfl_xor_sync(0xffffffffu, s, 1);
            s += __shfl_xor_sync(0xffffffffu, s, 2);
            float inv = 1.0f / s;
            float a0 = e0 * inv, a1 = e1 * inv;  // attn[mq][2g], attn[mq][2g+1]

            if (w == 0)
                *(float2*)&arim[((size_t)t * B_ + b) * 64 + lane * 2] =
                    make_float2(a0, a1);

            // A_comm[n=w][h] = sum_mm attn[mm][w] * VcT[mm][h]
            int n = w;
            float av = (n & 1) ? a1 : a0;
            ull cx = 0, cy = 0;
#pragma unroll
            for (int mm = 0; mm < 8; mm++) {
                float a = __shfl_sync(0xffffffffu, av, mm * 4 + (n >> 1));
                ull ap = pack2(a, a);
                ulonglong2 vc = *(const ulonglong2*)&sm.VcT[p][mm][lane * 4];
                cx = ffma2(ap, vc.x, cx);
                cy = ffma2(ap, vc.y, cy);
            }
            float2 c01 = unpack2(cx), c23 = unpack2(cy);
            float4 ac = make_float4(c01.x, c01.y, c23.x, c23.y);
            float4 hn = make_float4(hin.x + ac.x, hin.y + ac.y,
                                    hin.z + ac.z, hin.w + ac.w);
            *(float4*)&sm.Hst[n][lane * 4] = hn;
            size_t base = (((size_t)t * B_ + b) * M_ + n) * H_ + lane * 4;
            *(float4*)&hid[base] = hn;
            *(float4*)&acomm[base] = ac;
        }
        __syncwarp();   // Hst cross-lane visibility for next step's phase A
    }
}

// ---------------------------------------------------------------------------
// k_out v3: 128x128 tile, BK=16, register-prefetch double buffering, f32x2.
// grid 512, 256 threads.
// ---------------------------------------------------------------------------
__global__ __launch_bounds__(256) void k_out(const float* __restrict__ hid,
        const float* __restrict__ Wo, const float* __restrict__ bo,
        float* __restrict__ outp) {
    __shared__ float sAT[16][132];   // [k][row]
    __shared__ float sB[16][132];    // [k][o]
    int r0 = blockIdx.x * 128;
    int tid = threadIdx.x;
    int tx = tid & 15, ty = tid >> 4;

    int lrow = tid >> 1;            // 0..127
    int lkq  = (tid & 1) * 8;       // 0 or 8
    const float* aptr = hid + (size_t)(r0 + lrow) * 1024 + lkq;
    const float* bptr = Wo + (size_t)lrow * 1024 + lkq;

    ull acc[8][4];
#pragma unroll
    for (int a = 0; a < 8; a++)
#pragma unroll
        for (int c = 0; c < 4; c++) acc[a][c] = 0ull;

    float4 ra0 = *(const float4*)aptr;
    float4 ra1 = *(const float4*)(aptr + 4);
    float4 rb0 = *(const float4*)bptr;
    float4 rb1 = *(const float4*)(bptr + 4);

    for (int kc = 0; kc < 1024; kc += 16) {
        sAT[lkq + 0][lrow] = ra0.x; sAT[lkq + 1][lrow] = ra0.y;
        sAT[lkq + 2][lrow] = ra0.z; sAT[lkq + 3][lrow] = ra0.w;
        sAT[lkq + 4][lrow] = ra1.x; sAT[lkq + 5][lrow] = ra1.y;
        sAT[lkq + 6][lrow] = ra1.z; sAT[lkq + 7][lrow] = ra1.w;
        sB[lkq + 0][lrow] = rb0.x; sB[lkq + 1][lrow] = rb0.y;
        sB[lkq + 2][lrow] = rb0.z; sB[lkq + 3][lrow] = rb0.w;
        sB[lkq + 4][lrow] = rb1.x; sB[lkq + 5][lrow] = rb1.y;
        sB[lkq + 6][lrow] = rb1.z; sB[lkq + 7][lrow] = rb1.w;
        __syncthreads();
        if (kc + 16 < 1024) {
            aptr += 16; bptr += 16;
            ra0 = *(const float4*)aptr; ra1 = *(const float4*)(aptr + 4);
            rb0 = *(const float4*)bptr; rb1 = *(const float4*)(bptr + 4);
        }
#pragma unroll
        for (int k = 0; k < 16; k++) {
            float4 av0 = *(const float4*)&sAT[k][ty * 8];
            float4 av1 = *(const float4*)&sAT[k][ty * 8 + 4];
            float4 bv0 = *(const float4*)&sB[k][tx * 4];
            float4 bv1 = *(const float4*)&sB[k][64 + tx * 4];
            ull bb0 = pack2(bv0.x, bv0.y), bb1 = pack2(bv0.z, bv0.w);
            ull bb2 = pack2(bv1.x, bv1.y), bb3 = pack2(bv1.z, bv1.w);
            float av[8] = {av0.x, av0.y, av0.z, av0.w, av1.x, av1.y, av1.z, av1.w};
#pragma unroll
            for (int rr = 0; rr < 8; rr++) {
                ull ap = pack2(av[rr], av[rr]);
                acc[rr][0] = ffma2(ap, bb0, acc[rr][0]);
                acc[rr][1] = ffma2(ap, bb1, acc[rr][1]);
                acc[rr][2] = ffma2(ap, bb2, acc[rr][2]);
                acc[rr][3] = ffma2(ap, bb3, acc[rr][3]);
            }
        }
        __syncthreads();
    }
    float4 b4a = *(const float4*)&bo[tx * 4];
    float4 b4b = *(const float4*)&bo[64 + tx * 4];
#pragma unroll
    for (int rr = 0; rr < 8; rr++) {
        int rg = r0 + ty * 8 + rr;
        int t = rg >> 7, b = rg & 127;
        float2 v0 = unpack2(acc[rr][0]), v1 = unpack2(acc[rr][1]);
        float2 v2 = unpack2(acc[rr][2]), v3 = unpack2(acc[rr][3]);
        float* orow = outp + ((size_t)b * 512 + t) * 128;
        *(float4*)&orow[tx * 4] =
            make_float4(v0.x + b4a.x, v0.y + b4a.y, v1.x + b4a.z, v1.y + b4a.w);
        *(float4*)&orow[64 + tx * 4] =
            make_float4(v2.x + b4b.x, v2.y + b4b.y, v3.x + b4b.z, v3.y + b4b.w);
    }
}

// ---------------------------------------------------------------------------
extern "C" void kernel_launch(void* const* d_in, const int* in_sizes, int n_in,
                              void* d_out, int out_size) {
    const float* x    = (const float*)d_in[0];
    const float* Wp   = (const float*)d_in[1];
    const float* bp   = (const float*)d_in[2];
    const float* U    = (const float*)d_in[3];
    const float* V    = (const float*)d_in[4];
    const float* cb   = (const float*)d_in[5];
    const float* Win  = (const float*)d_in[6];
    const float* WQ   = (const float*)d_in[7];
    const float* WK   = (const float*)d_in[8];
    const float* WV   = (const float*)d_in[9];
    const float* Wo   = (const float*)d_in[10];
    const float* bo   = (const float*)d_in[11];

    float* out = (float*)d_out;
    float* outputs = out + OFF_OUT;
    float* hid     = out + OFF_HID;
    float* ain     = out + OFF_AIN;
    float* acomm   = out + OFF_ACOMM;
    float* arim    = out + OFF_ARIM;

    cudaFuncSetAttribute(k_rnn, cudaFuncAttributeMaxDynamicSharedMemorySize,
                         (int)sizeof(Smem3));
    cudaFuncSetAttribute(k_pre, cudaFuncAttributeMaxDynamicSharedMemorySize,
                         PRE_SMEM);

    k_weff<<<dim3(2, 8), 256>>>(Win, Wp);
    k_pre<<<1024, 256, PRE_SMEM>>>(x, Win, bp, cb, ain);
    k_rnn<<<128, 256, sizeof(Smem3)>>>(U, V, WQ, WK, WV, hid, acomm, arim);
    k_out<<<512, 256>>>(hid, Wo, bo, outputs);
}

// round 11
// speedup vs baseline: 1.0667x; 1.0322x over previous
#include <cuda_runtime.h>
#include <cuda_bf16.h>
#include <cstdint>

#define B_ 128
#define S_ 512
#define I_ 128
#define H_ 128
#define M_ 8
#define KD_ 16
#define R_ 16
#define O_ 128

// output region offsets (floats), concatenated in reference return order
#define OFF_OUT   ((size_t)0)                 // [B,S,O]      8388608
#define OFF_HID   ((size_t)8388608)           // [S,B,M,H]   67108864
#define OFF_AIN   ((size_t)75497472)          // [S,B,M,H]   67108864
#define OFF_ACOMM ((size_t)142606336)         // [S,B,M,H]   67108864
#define OFF_ARIM  ((size_t)209715200)         // [S,B,M,M]    4194304

__device__ float g_P[(size_t)S_ * B_ * M_ * H_];   // precomputed input_part + biases
__device__ float g_Weff[M_ * I_ * H_];             // W_in @ Wp^T per mechanism

typedef unsigned long long ull;

__device__ __forceinline__ ull ffma2(ull a, ull b, ull c) {
    ull d;
    asm("fma.rn.f32x2 %0, %1, %2, %3;" : "=l"(d) : "l"(a), "l"(b), "l"(c));
    return d;
}
__device__ __forceinline__ ull fadd2(ull a, ull b) {
    ull d;
    asm("add.rn.f32x2 %0, %1, %2;" : "=l"(d) : "l"(a), "l"(b));
    return d;
}
__device__ __forceinline__ ull pack2(float x, float y) {
    ull d; asm("mov.b64 %0, {%1, %2};" : "=l"(d) : "f"(x), "f"(y)); return d;
}
__device__ __forceinline__ float2 unpack2(ull v) {
    float2 r; asm("mov.b64 {%0, %1}, %2;" : "=f"(r.x), "=f"(r.y) : "l"(v)); return r;
}
__device__ __forceinline__ float tanh_fast(float x) {
    float e = __expf(2.0f * x);
    return 1.0f - 2.0f / (e + 1.0f);
}
__device__ __forceinline__ void cp16(void* s, const void* g) {
    unsigned ds = (unsigned)__cvta_generic_to_shared(s);
    asm volatile("cp.async.cg.shared.global [%0], [%1], 16;" :: "r"(ds), "l"(g));
}

// ---------------------------------------------------------------------------
// k_weff: Weff[m][i][o] = sum_h Win[m][i][h] * Wp[m][o][h].  grid (2,8), 256t
// ---------------------------------------------------------------------------
__global__ void k_weff(const float* __restrict__ Win, const float* __restrict__ Wp) {
    __shared__ float sA[64][36];
    __shared__ float sBt[32][132];
    int m = blockIdx.y;
    int i0 = blockIdx.x * 64;
    int tid = threadIdx.x;
    int ty = tid >> 5, tx = tid & 31;
    int w = tid >> 5, lane = tid & 31;

    float acc[8][4];
#pragma unroll
    for (int a = 0; a < 8; a++)
#pragma unroll
        for (int c = 0; c < 4; c++) acc[a][c] = 0.f;

    const float* A = Win + m * 16384;
    const float* Bm = Wp + m * 16384;

    for (int kc = 0; kc < 128; kc += 32) {
        {
            int row = tid >> 2, cs = (tid & 3) * 8;
            const float* ap = A + (i0 + row) * 128 + kc + cs;
            *(float4*)&sA[row][cs]     = *(const float4*)ap;
            *(float4*)&sA[row][cs + 4] = *(const float4*)(ap + 4);
        }
        {
            int og = lane >> 3, ii0 = (lane & 7) * 4;
#pragma unroll
            for (int it = 0; it < 4; it++) {
                int o = (w << 4) + og + (it << 2);
                float4 v = *(const float4*)(Bm + o * 128 + kc + ii0);
                sBt[ii0 + 0][o] = v.x; sBt[ii0 + 1][o] = v.y;
                sBt[ii0 + 2][o] = v.z; sBt[ii0 + 3][o] = v.w;
            }
        }
        __syncthreads();
#pragma unroll 8
        for (int kk = 0; kk < 32; kk++) {
            float4 wv = *(float4*)&sBt[kk][tx * 4];
#pragma unroll
            for (int rr = 0; rr < 8; rr++) {
                float av = sA[ty * 8 + rr][kk];
                acc[rr][0] += av * wv.x; acc[rr][1] += av * wv.y;
                acc[rr][2] += av * wv.z; acc[rr][3] += av * wv.w;
            }
        }
        __syncthreads();
    }
    float* dst = g_Weff + m * 16384;
#pragma unroll
    for (int rr = 0; rr < 8; rr++) {
        float4 v = make_float4(acc[rr][0], acc[rr][1], acc[rr][2], acc[rr][3]);
        *(float4*)&dst[(i0 + ty * 8 + rr) * 128 + tx * 4] = v;
    }
}

// ---------------------------------------------------------------------------
// k_pre v4: one block = 64 (t,b)-rows, all 8 mechanisms; 32 flattened chunks
// with register-prefetch of the next W tiles across the barrier.
// grid 1024, 256 threads, dynamic smem (67.5KB).
// ---------------------------------------------------------------------------
#define PRE_SMEM ((64 * 132 + 2 * 32 * 132) * 4)

__global__ __launch_bounds__(256) void k_pre(const float* __restrict__ x,
        const float* __restrict__ Win, const float* __restrict__ bp,
        const float* __restrict__ cb, float* __restrict__ ain) {
    extern __shared__ float ps[];
    float (*sX)[132]  = (float(*)[132])ps;                // [64][132]
    float (*sW1)[132] = (float(*)[132])(ps + 64 * 132);   // [32][132]
    float (*sW2)[132] = (float(*)[132])(ps + 96 * 132);   // [32][132]

    int r0 = blockIdx.x * 64;
    int t = r0 >> 7, b0 = r0 & 127;
    int tid = threadIdx.x;
    int ty = tid >> 5, tx = tid & 31;

    // load X tile once: 64 rows x 128
    {
        int row = tid >> 2, c0 = (tid & 3) * 32;
        const float* xp = x + ((size_t)(b0 + row) * 512 + t) * 128 + c0;
#pragma unroll
        for (int j = 0; j < 8; j++)
            *(float4*)&sX[row][c0 + 4 * j] = *(const float4*)(xp + 4 * j);
    }

    int iw = tid >> 3, hw = (tid & 7) * 16;   // W-tile load coords
    float4 rw1[4], rw2[4];
    {
        const float* p1 = Win + iw * 128 + hw;          // m=0, kc=0
        const float* p2 = g_Weff + iw * 128 + hw;
#pragma unroll
        for (int j = 0; j < 4; j++) {
            rw1[j] = *(const float4*)(p1 + 4 * j);
            rw2[j] = *(const float4*)(p2 + 4 * j);
        }
    }

    ull acc1[8][2], acc2[8][2];
#pragma unroll
    for (int a = 0; a < 8; a++) {
        acc1[a][0] = 0; acc1[a][1] = 0; acc2[a][0] = 0; acc2[a][1] = 0;
    }
    __syncthreads();   // X tile ready

    for (int cc = 0; cc < 32; cc++) {
        int m = cc >> 2, kc = (cc & 3) * 32;
#pragma unroll
        for (int j = 0; j < 4; j++) {
            *(float4*)&sW1[iw][hw + 4 * j] = rw1[j];
            *(float4*)&sW2[iw][hw + 4 * j] = rw2[j];
        }
        __syncthreads();
        if (cc + 1 < 32) {
            int m2 = (cc + 1) >> 2, kc2 = ((cc + 1) & 3) * 32;
            const float* p1 = Win + m2 * 16384 + (kc2 + iw) * 128 + hw;
            const float* p2 = g_Weff + m2 * 16384 + (kc2 + iw) * 128 + hw;
#pragma unroll
            for (int j = 0; j < 4; j++) {
                rw1[j] = *(const float4*)(p1 + 4 * j);
                rw2[j] = *(const float4*)(p2 + 4 * j);
            }
        }
#pragma unroll 8
        for (int kk = 0; kk < 32; kk++) {
            ulonglong2 w1 = *(const ulonglong2*)&sW1[kk][tx * 4];
            ulonglong2 w2 = *(const ulonglong2*)&sW2[kk][tx * 4];
#pragma unroll
            for (int rr = 0; rr < 8; rr++) {
                float xv = sX[ty * 8 + rr][kc + kk];
                ull xp2 = pack2(xv, xv);
                acc1[rr][0] = ffma2(xp2, w1.x, acc1[rr][0]);
                acc1[rr][1] = ffma2(xp2, w1.y, acc1[rr][1]);
                acc2[rr][0] = ffma2(xp2, w2.x, acc2[rr][0]);
                acc2[rr][1] = ffma2(xp2, w2.y, acc2[rr][1]);
            }
        }
        __syncthreads();
        if ((cc & 3) == 3) {
            float4 bi = *(const float4*)&bp[m * 128 + tx * 4];
            float4 ci = *(const float4*)&cb[m * 128 + tx * 4];
            float4 bias = make_float4(bi.x + ci.x, bi.y + ci.y,
                                      bi.z + ci.z, bi.w + ci.w);
#pragma unroll
            for (int rr = 0; rr < 8; rr++) {
                size_t gr = r0 + ty * 8 + rr;
                size_t base = (gr * 8 + m) * 128 + tx * 4;
                float2 a0 = unpack2(acc1[rr][0]), a1 = unpack2(acc1[rr][1]);
                float2 p0 = unpack2(acc2[rr][0]), p1 = unpack2(acc2[rr][1]);
                *(float4*)&ain[base] = make_float4(a0.x, a0.y, a1.x, a1.y);
                *(float4*)&g_P[base] = make_float4(p0.x + bias.x, p0.y + bias.y,
                                                   p1.x + bias.z, p1.y + bias.w);
                acc1[rr][0] = 0; acc1[rr][1] = 0;
                acc2[rr][0] = 0; acc2[rr][1] = 0;
            }
        }
    }
}

// ---------------------------------------------------------------------------
// k_rnn v3c: R7 structure + diag in registers + 4-way split accumulation
// chains in all phases (halves exposed FFMA dependency latency).
// 128 blocks, 256 threads.
// ---------------------------------------------------------------------------
struct Smem3 {
    float4 Ut4[M_][16][32];       // 65536 B: Ut4[m][i][lane].j = U[m][hf*64+4i+j][r]
    float V[M_][R_][H_];          // 65536 B
    float Hst[M_][H_];            // 4 KB
    float Hin[M_][H_];            // 4 KB
    float VcT[2][M_][H_];         // 8 KB (parity)
    float P[4][M_ * H_];          // 16 KB ring
    float KQ[2][M_][33];          // parity
};

__global__ __launch_bounds__(256) void k_rnn(
        const float* __restrict__ U, const float* __restrict__ V,
        const float* __restrict__ WQ, const float* __restrict__ WK,
        const float* __restrict__ WV,
        float* __restrict__ hid, float* __restrict__ acomm,
        float* __restrict__ arim) {
    extern __shared__ char raw[];
    Smem3& sm = *reinterpret_cast<Smem3*>(raw);
    int tid = threadIdx.x;
    int b = blockIdx.x;
    int w = tid >> 5, lane = tid & 31;
    const int m = w;
    const int r = lane & 15, hf = lane >> 4;

    // -------- init --------
    {
#pragma unroll
        for (int i = 0; i < 16; i++) {
            int hb = hf * 64 + i * 4;
            float4 v;
            v.x = U[((size_t)m * 128 + hb + 0) * 16 + r];
            v.y = U[((size_t)m * 128 + hb + 1) * 16 + r];
            v.z = U[((size_t)m * 128 + hb + 2) * 16 + r];
            v.w = U[((size_t)m * 128 + hb + 3) * 16 + r];
            sm.Ut4[m][i][lane] = v;
        }
    }
    for (int i = tid * 4; i < M_ * R_ * H_; i += 256 * 4)
        *(float4*)((float*)sm.V + i) = *(const float4*)(V + i);
    for (int e = tid; e < M_ * H_; e += 256) {
        int mm = e >> 7, h = e & 127;
        sm.Hst[mm][h] = 0.f;
    }
    float4 dreg;
    {
        int h = lane * 4;
        dreg.x = WV[((size_t)m * H_ + h + 0) * H_ + h + 0];
        dreg.y = WV[((size_t)m * H_ + h + 1) * H_ + h + 1];
        dreg.z = WV[((size_t)m * H_ + h + 2) * H_ + h + 2];
        dreg.w = WV[((size_t)m * H_ + h + 3) * H_ + h + 3];
    }
    ull wreg[64];
    {
        const float* src = (lane < 16) ? (WK + m * H_ * KD_ + lane)
                                       : (WQ + m * H_ * KD_ + (lane - 16));
#pragma unroll
        for (int hp = 0; hp < 64; hp++)
            wreg[hp] = pack2(src[(2 * hp) * KD_], src[(2 * hp + 1) * KD_]);
    }
    const float* Pb = g_P + (size_t)b * 1024;
#pragma unroll
    for (int pt = 0; pt < 3; pt++) {
        cp16(&sm.P[pt][tid * 4], Pb + (size_t)pt * (B_ * 1024) + tid * 4);
        asm volatile("cp.async.commit_group;");
    }
    __syncthreads();

    for (int t = 0; t < S_; t++) {
        const int p = t & 1;
        if (t + 3 < S_)
            cp16(&sm.P[(t + 3) & 3][tid * 4],
                 Pb + (size_t)(t + 3) * (B_ * 1024) + tid * 4);
        asm volatile("cp.async.commit_group;");
        asm volatile("cp.async.wait_group 3;");

        // ---- phase A: rec = (H @ U) @ V ; Hin = tanh(P+rec) ; VcT = Hin*diag
        float4 hin;
        {
            const float4* Hc = (const float4*)&sm.Hst[m][hf * 64];
            ull s0 = 0, s1 = 0, s2 = 0, s3 = 0;     // 4 chains of 8
#pragma unroll
            for (int i = 0; i < 16; i += 2) {
                float4 u0 = sm.Ut4[m][i][lane];
                float4 h0 = Hc[i];
                float4 u1 = sm.Ut4[m][i + 1][lane];
                float4 h1 = Hc[i + 1];
                s0 = ffma2(pack2(h0.x, h0.y), pack2(u0.x, u0.y), s0);
                s1 = ffma2(pack2(h0.z, h0.w), pack2(u0.z, u0.w), s1);
                s2 = ffma2(pack2(h1.x, h1.y), pack2(u1.x, u1.y), s2);
                s3 = ffma2(pack2(h1.z, h1.w), pack2(u1.z, u1.w), s3);
            }
            ull sA_ = fadd2(fadd2(s0, s1), fadd2(s2, s3));
            float2 tA = unpack2(sA_);
            float partial = tA.x + tA.y;
            partial += __shfl_xor_sync(0xffffffffu, partial, 16);
            ull ax = 0, ay = 0, ax2 = 0, ay2 = 0;   // 4 chains of 8
#pragma unroll
            for (int rr = 0; rr < 16; rr += 2) {
                float t0 = __shfl_sync(0xffffffffu, partial, rr);
                float t1 = __shfl_sync(0xffffffffu, partial, rr + 1);
                ull tp0 = pack2(t0, t0), tp1 = pack2(t1, t1);
                ulonglong2 v0 = *(const ulonglong2*)&sm.V[m][rr][lane * 4];
                ulonglong2 v1 = *(const ulonglong2*)&sm.V[m][rr + 1][lane * 4];
                ax  = ffma2(tp0, v0.x, ax);
                ay  = ffma2(tp0, v0.y, ay);
                ax2 = ffma2(tp1, v1.x, ax2);
                ay2 = ffma2(tp1, v1.y, ay2);
            }
            ax = fadd2(ax, ax2);
            ay = fadd2(ay, ay2);
            float2 a01 = unpack2(ax), a23 = unpack2(ay);
            float4 pv = *(const float4*)&sm.P[t & 3][tid * 4];
            hin.x = tanh_fast(pv.x + a01.x);
            hin.y = tanh_fast(pv.y + a01.y);
            hin.z = tanh_fast(pv.z + a23.x);
            hin.w = tanh_fast(pv.w + a23.y);
            *(float4*)&sm.Hin[m][lane * 4] = hin;
            *(float4*)&sm.VcT[p][m][lane * 4] =
                make_float4(hin.x * dreg.x, hin.y * dreg.y,
                            hin.z * dreg.z, hin.w * dreg.w);
        }
        __syncwarp();

        // ---- phase B: K/Q projection, 4 chains of 16
        {
            ull a0 = 0, a1 = 0, a2 = 0, a3 = 0;
            const ulonglong2* hb = (const ulonglong2*)&sm.Hin[m][0];
#pragma unroll
            for (int i = 0; i < 32; i += 2) {
                ulonglong2 h0 = hb[i];
                ulonglong2 h1 = hb[i + 1];
                a0 = ffma2(h0.x, wreg[2 * i], a0);
                a1 = ffma2(h0.y, wreg[2 * i + 1], a1);
                a2 = ffma2(h1.x, wreg[2 * i + 2], a2);
                a3 = ffma2(h1.y, wreg[2 * i + 3], a3);
            }
            ull sB_ = fadd2(fadd2(a0, a1), fadd2(a2, a3));
            float2 sb = unpack2(sB_);
            sm.KQ[p][m][lane] = sb.x + sb.y;
        }
        __syncthreads();

        // ---- phase C: per-warp redundant 8x8 attention + comm + update
        {
            int mq = lane >> 2, g = lane & 3;   // lane owns logits[mq][2g],[2g+1]
            float L0a = 0.f, L0b = 0.f, L1a = 0.f, L1b = 0.f;
#pragma unroll
            for (int k = 0; k < 16; k += 2) {
                float q0 = sm.KQ[p][mq][16 + k];
                float q1 = sm.KQ[p][mq][16 + k + 1];
                L0a += q0 * sm.KQ[p][2 * g][k];
                L0b += q1 * sm.KQ[p][2 * g][k + 1];
                L1a += q0 * sm.KQ[p][2 * g + 1][k];
                L1b += q1 * sm.KQ[p][2 * g + 1][k + 1];
            }
            float L0 = (L0a + L0b) * 0.25f, L1 = (L1a + L1b) * 0.25f;
            float mx = fmaxf(L0, L1);
            mx = fmaxf(mx, __shfl_xor_sync(0xffffffffu, mx, 1));
            mx = fmaxf(mx, __shfl_xor_sync(0xffffffffu, mx, 2));
            float e0 = __expf(L0 - mx), e1 = __expf(L1 - mx);
            float s = e0 + e1;
            s += __shfl_xor_sync(0xffffffffu, s, 1);
            s += __shfl_xor_sync(0xffffffffu, s, 2);
            float inv = 1.0f / s;
            float a0 = e0 * inv, a1 = e1 * inv;  // attn[mq][2g], attn[mq][2g+1]

            if (w == 0)
                *(float2*)&arim[((size_t)t * B_ + b) * 64 + lane * 2] =
                    make_float2(a0, a1);

            // A_comm[n=w][h] = sum_mm attn[mm][w] * VcT[mm][h], 4 chains of 4
            int n = w;
            float av = (n & 1) ? a1 : a0;
            ull cx = 0, cy = 0, cx2 = 0, cy2 = 0;
#pragma unroll
            for (int mm = 0; mm < 8; mm += 2) {
                float aa = __shfl_sync(0xffffffffu, av, mm * 4 + (n >> 1));
                float ab = __shfl_sync(0xffffffffu, av, (mm + 1) * 4 + (n >> 1));
                ull apa = pack2(aa, aa), apb = pack2(ab, ab);
                ulonglong2 vc0 = *(const ulonglong2*)&sm.VcT[p][mm][lane * 4];
                ulonglong2 vc1 = *(const ulonglong2*)&sm.VcT[p][mm + 1][lane * 4];
                cx  = ffma2(apa, vc0.x, cx);
                cy  = ffma2(apa, vc0.y, cy);
                cx2 = ffma2(apb, vc1.x, cx2);
                cy2 = ffma2(apb, vc1.y, cy2);
            }
            cx = fadd2(cx, cx2);
            cy = fadd2(cy, cy2);
            float2 c01 = unpack2(cx), c23 = unpack2(cy);
            float4 ac = make_float4(c01.x, c01.y, c23.x, c23.y);
            float4 hn = make_float4(hin.x + ac.x, hin.y + ac.y,
                                    hin.z + ac.z, hin.w + ac.w);
            *(float4*)&sm.Hst[n][lane * 4] = hn;
            size_t base = (((size_t)t * B_ + b) * M_ + n) * H_ + lane * 4;
            *(float4*)&hid[base] = hn;
            *(float4*)&acomm[base] = ac;
        }
        __syncwarp();   // Hst cross-lane visibility for next step's phase A
    }
}

// ---------------------------------------------------------------------------
// k_out v3: 128x128 tile, BK=16, register-prefetch double buffering, f32x2.
// grid 512, 256 threads.
// ---------------------------------------------------------------------------
__global__ __launch_bounds__(256) void k_out(const float* __restrict__ hid,
        const float* __restrict__ Wo, const float* __restrict__ bo,
        float* __restrict__ outp) {
    __shared__ float sAT[16][132];   // [k][row]
    __shared__ float sB[16][132];    // [k][o]
    int r0 = blockIdx.x * 128;
    int tid = threadIdx.x;
    int tx = tid & 15, ty = tid >> 4;

    int lrow = tid >> 1;            // 0..127
    int lkq  = (tid & 1) * 8;       // 0 or 8
    const float* aptr = hid + (size_t)(r0 + lrow) * 1024 + lkq;
    const float* bptr = Wo + (size_t)lrow * 1024 + lkq;

    ull acc[8][4];
#pragma unroll
    for (int a = 0; a < 8; a++)
#pragma unroll
        for (int c = 0; c < 4; c++) acc[a][c] = 0ull;

    float4 ra0 = *(const float4*)aptr;
    float4 ra1 = *(const float4*)(aptr + 4);
    float4 rb0 = *(const float4*)bptr;
    float4 rb1 = *(const float4*)(bptr + 4);

    for (int kc = 0; kc < 1024; kc += 16) {
        sAT[lkq + 0][lrow] = ra0.x; sAT[lkq + 1][lrow] = ra0.y;
        sAT[lkq + 2][lrow] = ra0.z; sAT[lkq + 3][lrow] = ra0.w;
        sAT[lkq + 4][lrow] = ra1.x; sAT[lkq + 5][lrow] = ra1.y;
        sAT[lkq + 6][lrow] = ra1.z; sAT[lkq + 7][lrow] = ra1.w;
        sB[lkq + 0][lrow] = rb0.x; sB[lkq + 1][lrow] = rb0.y;
        sB[lkq + 2][lrow] = rb0.z; sB[lkq + 3][lrow] = rb0.w;
        sB[lkq + 4][lrow] = rb1.x; sB[lkq + 5][lrow] = rb1.y;
        sB[lkq + 6][lrow] = rb1.z; sB[lkq + 7][lrow] = rb1.w;
        __syncthreads();
        if (kc + 16 < 1024) {
            aptr += 16; bptr += 16;
            ra0 = *(const float4*)aptr; ra1 = *(const float4*)(aptr + 4);
            rb0 = *(const float4*)bptr; rb1 = *(const float4*)(bptr + 4);
        }
#pragma unroll
        for (int k = 0; k < 16; k++) {
            float4 av0 = *(const float4*)&sAT[k][ty * 8];
            float4 av1 = *(const float4*)&sAT[k][ty * 8 + 4];
            float4 bv0 = *(const float4*)&sB[k][tx * 4];
            float4 bv1 = *(const float4*)&sB[k][64 + tx * 4];
            ull bb0 = pack2(bv0.x, bv0.y), bb1 = pack2(bv0.z, bv0.w);
            ull bb2 = pack2(bv1.x, bv1.y), bb3 = pack2(bv1.z, bv1.w);
            float av[8] = {av0.x, av0.y, av0.z, av0.w, av1.x, av1.y, av1.z, av1.w};
#pragma unroll
            for (int rr = 0; rr < 8; rr++) {
                ull ap = pack2(av[rr], av[rr]);
                acc[rr][0] = ffma2(ap, bb0, acc[rr][0]);
                acc[rr][1] = ffma2(ap, bb1, acc[rr][1]);
                acc[rr][2] = ffma2(ap, bb2, acc[rr][2]);
                acc[rr][3] = ffma2(ap, bb3, acc[rr][3]);
            }
        }
        __syncthreads();
    }
    float4 b4a = *(const float4*)&bo[tx * 4];
    float4 b4b = *(const float4*)&bo[64 + tx * 4];
#pragma unroll
    for (int rr = 0; rr < 8; rr++) {
        int rg = r0 + ty * 8 + rr;
        int t = rg >> 7, b = rg & 127;
        float2 v0 = unpack2(acc[rr][0]), v1 = unpack2(acc[rr][1]);
        float2 v2 = unpack2(acc[rr][2]), v3 = unpack2(acc[rr][3]);
        float* orow = outp + ((size_t)b * 512 + t) * 128;
        *(float4*)&orow[tx * 4] =
            make_float4(v0.x + b4a.x, v0.y + b4a.y, v1.x + b4a.z, v1.y + b4a.w);
        *(float4*)&orow[64 + tx * 4] =
            make_float4(v2.x + b4b.x, v2.y + b4b.y, v3.x + b4b.z, v3.y + b4b.w);
    }
}

// ---------------------------------------------------------------------------
extern "C" void kernel_launch(void* const* d_in, const int* in_sizes, int n_in,
                              void* d_out, int out_size) {
    const float* x    = (const float*)d_in[0];
    const float* Wp   = (const float*)d_in[1];
    const float* bp   = (const float*)d_in[2];
    const float* U    = (const float*)d_in[3];
    const float* V    = (const float*)d_in[4];
    const float* cb   = (const float*)d_in[5];
    const float* Win  = (const float*)d_in[6];
    const float* WQ   = (const float*)d_in[7];
    const float* WK   = (const float*)d_in[8];
    const float* WV   = (const float*)d_in[9];
    const float* Wo   = (const float*)d_in[10];
    const float* bo   = (const float*)d_in[11];

    float* out = (float*)d_out;
    float* outputs = out + OFF_OUT;
    float* hid     = out + OFF_HID;
    float* ain     = out + OFF_AIN;
    float* acomm   = out + OFF_ACOMM;
    float* arim    = out + OFF_ARIM;

    cudaFuncSetAttribute(k_rnn, cudaFuncAttributeMaxDynamicSharedMemorySize,
                         (int)sizeof(Smem3));
    cudaFuncSetAttribute(k_pre, cudaFuncAttributeMaxDynamicSharedMemorySize,
                         PRE_SMEM);

    k_weff<<<dim3(2, 8), 256>>>(Win, Wp);
    k_pre<<<1024, 256, PRE_SMEM>>>(x, Win, bp, cb, ain);
    k_rnn<<<128, 256, sizeof(Smem3)>>>(U, V, WQ, WK, WV, hid, acomm, arim);
    k_out<<<512, 256>>>(hid, Wo, bo, outputs);
}

// round 14
// speedup vs baseline: 1.2749x; 1.1952x over previous
#include <cuda_runtime.h>
#include <cuda_bf16.h>
#include <cstdint>

#define B_ 128
#define S_ 512
#define I_ 128
#define H_ 128
#define M_ 8
#define KD_ 16
#define R_ 16
#define O_ 128

// output region offsets (floats), concatenated in reference return order
#define OFF_OUT   ((size_t)0)                 // [B,S,O]      8388608
#define OFF_HID   ((size_t)8388608)           // [S,B,M,H]   67108864
#define OFF_AIN   ((size_t)75497472)          // [S,B,M,H]   67108864
#define OFF_ACOMM ((size_t)142606336)         // [S,B,M,H]   67108864
#define OFF_ARIM  ((size_t)209715200)         // [S,B,M,M]    4194304

__device__ float g_P[(size_t)S_ * B_ * M_ * H_];   // precomputed input_part + biases
__device__ float g_Weff[M_ * I_ * H_];             // W_in @ Wp^T per mechanism
// bf16-split weights for k_pre_mma: [m][n(256)][k(128)], n<128 = Win col, n>=128 = Weff col
__device__ __nv_bfloat16 g_Wh[M_ * 256 * 128];
__device__ __nv_bfloat16 g_Wl[M_ * 256 * 128];
__device__ float g_bias[M_ * 128];                 // bp + cb

typedef unsigned long long ull;

__device__ __forceinline__ ull ffma2(ull a, ull b, ull c) {
    ull d;
    asm("fma.rn.f32x2 %0, %1, %2, %3;" : "=l"(d) : "l"(a), "l"(b), "l"(c));
    return d;
}
__device__ __forceinline__ ull fadd2(ull a, ull b) {
    ull d;
    asm("add.rn.f32x2 %0, %1, %2;" : "=l"(d) : "l"(a), "l"(b));
    return d;
}
__device__ __forceinline__ ull pack2(float x, float y) {
    ull d; asm("mov.b64 %0, {%1, %2};" : "=l"(d) : "f"(x), "f"(y)); return d;
}
__device__ __forceinline__ float2 unpack2(ull v) {
    float2 r; asm("mov.b64 {%0, %1}, %2;" : "=f"(r.x), "=f"(r.y) : "l"(v)); return r;
}
__device__ __forceinline__ float tanh_fast(float x) {
    float e = __expf(2.0f * x);
    return 1.0f - 2.0f / (e + 1.0f);
}
__device__ __forceinline__ void cp16(void* s, const void* g) {
    unsigned ds = (unsigned)__cvta_generic_to_shared(s);
    asm volatile("cp.async.cg.shared.global [%0], [%1], 16;" :: "r"(ds), "l"(g));
}
// mma.sync m16n8k16 bf16: D += A * B (D=C in-place)
__device__ __forceinline__ void mma_bf16(float* d, const uint32_t* a,
                                         uint32_t b0, uint32_t b1) {
    asm volatile(
        "mma.sync.aligned.m16n8k16.row.col.f32.bf16.bf16.f32 "
        "{%0,%1,%2,%3}, {%4,%5,%6,%7}, {%8,%9}, {%0,%1,%2,%3};"
        : "+f"(d[0]), "+f"(d[1]), "+f"(d[2]), "+f"(d[3])
        : "r"(a[0]), "r"(a[1]), "r"(a[2]), "r"(a[3]), "r"(b0), "r"(b1));
}

// ---------------------------------------------------------------------------
// k_weff: Weff[m][i][o] = sum_h Win[m][i][h] * Wp[m][o][h].  grid (2,8), 256t
// ---------------------------------------------------------------------------
__global__ void k_weff(const float* __restrict__ Win, const float* __restrict__ Wp) {
    __shared__ float sA[64][36];
    __shared__ float sBt[32][132];
    int m = blockIdx.y;
    int i0 = blockIdx.x * 64;
    int tid = threadIdx.x;
    int ty = tid >> 5, tx = tid & 31;
    int w = tid >> 5, lane = tid & 31;

    float acc[8][4];
#pragma unroll
    for (int a = 0; a < 8; a++)
#pragma unroll
        for (int c = 0; c < 4; c++) acc[a][c] = 0.f;

    const float* A = Win + m * 16384;
    const float* Bm = Wp + m * 16384;

    for (int kc = 0; kc < 128; kc += 32) {
        {
            int row = tid >> 2, cs = (tid & 3) * 8;
            const float* ap = A + (i0 + row) * 128 + kc + cs;
            *(float4*)&sA[row][cs]     = *(const float4*)ap;
            *(float4*)&sA[row][cs + 4] = *(const float4*)(ap + 4);
        }
        {
            int og = lane >> 3, ii0 = (lane & 7) * 4;
#pragma unroll
            for (int it = 0; it < 4; it++) {
                int o = (w << 4) + og + (it << 2);
                float4 v = *(const float4*)(Bm + o * 128 + kc + ii0);
                sBt[ii0 + 0][o] = v.x; sBt[ii0 + 1][o] = v.y;
                sBt[ii0 + 2][o] = v.z; sBt[ii0 + 3][o] = v.w;
            }
        }
        __syncthreads();
#pragma unroll 8
        for (int kk = 0; kk < 32; kk++) {
            float4 wv = *(float4*)&sBt[kk][tx * 4];
#pragma unroll
            for (int rr = 0; rr < 8; rr++) {
                float av = sA[ty * 8 + rr][kk];
                acc[rr][0] += av * wv.x; acc[rr][1] += av * wv.y;
                acc[rr][2] += av * wv.z; acc[rr][3] += av * wv.w;
            }
        }
        __syncthreads();
    }
    float* dst = g_Weff + m * 16384;
#pragma unroll
    for (int rr = 0; rr < 8; rr++) {
        float4 v = make_float4(acc[rr][0], acc[rr][1], acc[rr][2], acc[rr][3]);
        *(float4*)&dst[(i0 + ty * 8 + rr) * 128 + tx * 4] = v;
    }
}

// ---------------------------------------------------------------------------
// k_wcvt: convert [Win^T | Weff^T] to bf16 hi/lo, layout [m][n][k] (k-contig).
// grid (8, 8): x = k-chunk of 16, y = m. 256 threads (thread = n).
// ---------------------------------------------------------------------------
__global__ void k_wcvt(const float* __restrict__ Win, const float* __restrict__ bp,
                       const float* __restrict__ cb) {
    int m = blockIdx.y;
    int kc = blockIdx.x;
    int n = threadIdx.x;
#pragma unroll
    for (int kk = 0; kk < 16; kk++) {
        int k = kc * 16 + kk;
        float v = (n < 128) ? Win[m * 16384 + k * 128 + n]
                            : g_Weff[m * 16384 + k * 128 + (n - 128)];
        __nv_bfloat16 h = __float2bfloat16(v);
        __nv_bfloat16 l = __float2bfloat16(v - __bfloat162float(h));
        size_t o = ((size_t)m * 256 + n) * 128 + k;
        g_Wh[o] = h;
        g_Wl[o] = l;
    }
    if (kc == 0 && n < 128)
        g_bias[m * 128 + n] = bp[m * 128 + n] + cb[m * 128 + n];
}

// ---------------------------------------------------------------------------
// k_pre_mma: HMMA bf16-split GEMM. grid 1024 (64 b-rows x one t), 256 thr.
//   D[64 rows][256 n] = x * [Win | Weff], 3 split products, fp32 accum.
//   warps 0-3 -> ain (n 0..127), warps 4-7 -> g_P (+bias).
// smem: xh[64][136]bf16, xl same; 2 weight chunk buffers, each
//       hi[256][72]bf16 + lo[256][72]bf16. 16 chunks = (m, k-half).
// ---------------------------------------------------------------------------
#define XH_OFF   0
#define XL_OFF   17408
#define WB_OFF   34816
#define WB_SIZE  73728           // hi 36864 + lo 36864
#define WB_LO    36864
#define PM_SMEM  (34816 + 2 * 73728)

__device__ __forceinline__ void pm_issue_chunk(char* smbase, int c,
        int tid) {
    int m = c >> 1, kh = c & 1;
    char* buf = smbase + WB_OFF + (size_t)(c & 1) * WB_SIZE;
#pragma unroll
    for (int it = 0; it < 2; it++) {
        int i = tid + it * 256;
        int n = i & 255;
        int hi = (i < 256);
        const __nv_bfloat16* src = (hi ? g_Wh : g_Wl)
            + ((size_t)m * 256 + n) * 128 + kh * 64;
        char* dst = buf + (hi ? 0 : WB_LO) + n * 144;
#pragma unroll
        for (int j = 0; j < 8; j++)
            cp16(dst + j * 16, src + j * 8);
    }
    asm volatile("cp.async.commit_group;");
}

__global__ __launch_bounds__(256, 1) void k_pre_mma(const float* __restrict__ x,
        float* __restrict__ ain) {
    extern __shared__ char sm[];
    char* xh = sm + XH_OFF;
    char* xl = sm + XL_OFF;
    int tid = threadIdx.x, wid = tid >> 5, lane = tid & 31;
    int g = lane >> 2, tg = lane & 3;
    int r0 = blockIdx.x * 64;
    int t = r0 >> 7, b0 = r0 & 127;

    // ---- convert x tile (64 rows x 128 k) to bf16 hi/lo smem ----
    {
        int r = tid >> 2, c0 = (tid & 3) * 32;
        const float* xp = x + ((size_t)(b0 + r) * 512 + t) * 128 + c0;
        char* dh = xh + r * 272 + c0 * 2;
        char* dl = xl + r * 272 + c0 * 2;
#pragma unroll
        for (int j = 0; j < 32; j += 4) {
            float4 v = *(const float4*)(xp + j);
            float vv[4] = {v.x, v.y, v.z, v.w};
            union { __nv_bfloat16 b[4]; ull u; } ph, pl;
#pragma unroll
            for (int e = 0; e < 4; e++) {
                ph.b[e] = __float2bfloat16(vv[e]);
                pl.b[e] = __float2bfloat16(vv[e] - __bfloat162float(ph.b[e]));
            }
            *(ull*)(dh + j * 2) = ph.u;
            *(ull*)(dl + j * 2) = pl.u;
        }
    }

    // prologue: chunks 0, 1 in flight
    pm_issue_chunk(sm, 0, tid);
    pm_issue_chunk(sm, 1, tid);

    float acc[2][8][4];
#pragma unroll
    for (int a = 0; a < 2; a++)
#pragma unroll
        for (int b = 0; b < 8; b++)
#pragma unroll
            for (int c = 0; c < 4; c++) acc[a][b][c] = 0.f;

    for (int cc = 0; cc < 16; cc++) {
        int m = cc >> 1, kh = cc & 1;
        if (cc < 15) asm volatile("cp.async.wait_group 1;");
        else         asm volatile("cp.async.wait_group 0;");
        __syncthreads();     // chunk cc (and x on first iter) visible

        const char* wb  = sm + WB_OFF + (size_t)(cc & 1) * WB_SIZE;
        const char* wbl = wb + WB_LO;
#pragma unroll
        for (int ks = 0; ks < 4; ks++) {
            uint32_t aH[2][4], aL[2][4];
#pragma unroll
            for (int ng = 0; ng < 2; ng++) {
                int row = wid * 32 + ng * 16 + g;
                const char* ab = wb + row * 144 + (ks * 16 + tg * 2) * 2;
                aH[ng][0] = *(const uint32_t*)ab;
                aH[ng][1] = *(const uint32_t*)(ab + 8 * 144);
                aH[ng][2] = *(const uint32_t*)(ab + 16);
                aH[ng][3] = *(const uint32_t*)(ab + 8 * 144 + 16);
                const char* al = wbl + row * 144 + (ks * 16 + tg * 2) * 2;
                aL[ng][0] = *(const uint32_t*)al;
                aL[ng][1] = *(const uint32_t*)(al + 8 * 144);
                aL[ng][2] = *(const uint32_t*)(al + 16);
                aL[ng][3] = *(const uint32_t*)(al + 8 * 144 + 16);
            }
#pragma unroll
            for (int rt = 0; rt < 8; rt++) {
                uint32_t boff = (rt * 8 + g) * 272 + (kh * 64 + ks * 16 + tg * 2) * 2;
                uint32_t bh0 = *(const uint32_t*)(xh + boff);
                uint32_t bh1 = *(const uint32_t*)(xh + boff + 16);
                uint32_t bl0 = *(const uint32_t*)(xl + boff);
                uint32_t bl1 = *(const uint32_t*)(xl + boff + 16);
#pragma unroll
                for (int ng = 0; ng < 2; ng++) {
                    mma_bf16(acc[ng][rt], aH[ng], bh0, bh1);
                    mma_bf16(acc[ng][rt], aH[ng], bl0, bl1);
                    mma_bf16(acc[ng][rt], aL[ng], bh0, bh1);
                }
            }
        }

        if (kh) {
            // ---- epilogue for mechanism m ----
#pragma unroll
            for (int ng = 0; ng < 2; ng++) {
                int n = wid * 32 + ng * 16 + g;       // warp-uniform branch below
                int hcol = (n < 128) ? n : (n - 128);
                float* base = (n < 128) ? ain : g_P;
                float bA = 0.f, bB = 0.f;
                if (n >= 128) {
                    bA = g_bias[m * 128 + hcol];
                    bB = g_bias[m * 128 + hcol + 8];
                }
#pragma unroll
                for (int rt = 0; rt < 8; rt++) {
                    int br = rt * 8 + tg * 2;
                    size_t rb = ((size_t)((t * 128 + b0 + br) * 8 + m)) * 128;
                    base[rb + hcol]              = acc[ng][rt][0] + bA;
                    base[rb + 1024 + hcol]       = acc[ng][rt][1] + bA;
                    base[rb + hcol + 8]          = acc[ng][rt][2] + bB;
                    base[rb + 1024 + hcol + 8]   = acc[ng][rt][3] + bB;
                    acc[ng][rt][0] = 0.f; acc[ng][rt][1] = 0.f;
                    acc[ng][rt][2] = 0.f; acc[ng][rt][3] = 0.f;
                }
            }
        }
        __syncthreads();     // all done with buffer (cc&1) before overwrite
        if (cc + 2 < 16) pm_issue_chunk(sm, cc + 2, tid);
    }
}

// ---------------------------------------------------------------------------
// k_rnn v3c (R11): 128 blocks, 256 threads.
// ---------------------------------------------------------------------------
struct Smem3 {
    float4 Ut4[M_][16][32];
    float V[M_][R_][H_];
    float Hst[M_][H_];
    float Hin[M_][H_];
    float VcT[2][M_][H_];
    float P[4][M_ * H_];
    float KQ[2][M_][33];
};

__global__ __launch_bounds__(256) void k_rnn(
        const float* __restrict__ U, const float* __restrict__ V,
        const float* __restrict__ WQ, const float* __restrict__ WK,
        const float* __restrict__ WV,
        float* __restrict__ hid, float* __restrict__ acomm,
        float* __restrict__ arim) {
    extern __shared__ char raw[];
    Smem3& sm = *reinterpret_cast<Smem3*>(raw);
    int tid = threadIdx.x;
    int b = blockIdx.x;
    int w = tid >> 5, lane = tid & 31;
    const int m = w;
    const int r = lane & 15, hf = lane >> 4;

    {
#pragma unroll
        for (int i = 0; i < 16; i++) {
            int hb = hf * 64 + i * 4;
            float4 v;
            v.x = U[((size_t)m * 128 + hb + 0) * 16 + r];
            v.y = U[((size_t)m * 128 + hb + 1) * 16 + r];
            v.z = U[((size_t)m * 128 + hb + 2) * 16 + r];
            v.w = U[((size_t)m * 128 + hb + 3) * 16 + r];
            sm.Ut4[m][i][lane] = v;
        }
    }
    for (int i = tid * 4; i < M_ * R_ * H_; i += 256 * 4)
        *(float4*)((float*)sm.V + i) = *(const float4*)(V + i);
    for (int e = tid; e < M_ * H_; e += 256) {
        int mm = e >> 7, h = e & 127;
        sm.Hst[mm][h] = 0.f;
    }
    float4 dreg;
    {
        int h = lane * 4;
        dreg.x = WV[((size_t)m * H_ + h + 0) * H_ + h + 0];
        dreg.y = WV[((size_t)m * H_ + h + 1) * H_ + h + 1];
        dreg.z = WV[((size_t)m * H_ + h + 2) * H_ + h + 2];
        dreg.w = WV[((size_t)m * H_ + h + 3) * H_ + h + 3];
    }
    ull wreg[64];
    {
        const float* src = (lane < 16) ? (WK + m * H_ * KD_ + lane)
                                       : (WQ + m * H_ * KD_ + (lane - 16));
#pragma unroll
        for (int hp = 0; hp < 64; hp++)
            wreg[hp] = pack2(src[(2 * hp) * KD_], src[(2 * hp + 1) * KD_]);
    }
    const float* Pb = g_P + (size_t)b * 1024;
#pragma unroll
    for (int pt = 0; pt < 3; pt++) {
        cp16(&sm.P[pt][tid * 4], Pb + (size_t)pt * (B_ * 1024) + tid * 4);
        asm volatile("cp.async.commit_group;");
    }
    __syncthreads();

    for (int t = 0; t < S_; t++) {
        const int p = t & 1;
        if (t + 3 < S_)
            cp16(&sm.P[(t + 3) & 3][tid * 4],
                 Pb + (size_t)(t + 3) * (B_ * 1024) + tid * 4);
        asm volatile("cp.async.commit_group;");
        asm volatile("cp.async.wait_group 3;");

        float4 hin;
        {
            const float4* Hc = (const float4*)&sm.Hst[m][hf * 64];
            ull s0 = 0, s1 = 0, s2 = 0, s3 = 0;
#pragma unroll
            for (int i = 0; i < 16; i += 2) {
                float4 u0 = sm.Ut4[m][i][lane];
                float4 h0 = Hc[i];
                float4 u1 = sm.Ut4[m][i + 1][lane];
                float4 h1 = Hc[i + 1];
                s0 = ffma2(pack2(h0.x, h0.y), pack2(u0.x, u0.y), s0);
                s1 = ffma2(pack2(h0.z, h0.w), pack2(u0.z, u0.w), s1);
                s2 = ffma2(pack2(h1.x, h1.y), pack2(u1.x, u1.y), s2);
                s3 = ffma2(pack2(h1.z, h1.w), pack2(u1.z, u1.w), s3);
            }
            ull sA_ = fadd2(fadd2(s0, s1), fadd2(s2, s3));
            float2 tA = unpack2(sA_);
            float partial = tA.x + tA.y;
            partial += __shfl_xor_sync(0xffffffffu, partial, 16);
            ull ax = 0, ay = 0, ax2 = 0, ay2 = 0;
#pragma unroll
            for (int rr = 0; rr < 16; rr += 2) {
                float t0 = __shfl_sync(0xffffffffu, partial, rr);
                float t1 = __shfl_sync(0xffffffffu, partial, rr + 1);
                ull tp0 = pack2(t0, t0), tp1 = pack2(t1, t1);
                ulonglong2 v0 = *(const ulonglong2*)&sm.V[m][rr][lane * 4];
                ulonglong2 v1 = *(const ulonglong2*)&sm.V[m][rr + 1][lane * 4];
                ax  = ffma2(tp0, v0.x, ax);
                ay  = ffma2(tp0, v0.y, ay);
                ax2 = ffma2(tp1, v1.x, ax2);
                ay2 = ffma2(tp1, v1.y, ay2);
            }
            ax = fadd2(ax, ax2);
            ay = fadd2(ay, ay2);
            float2 a01 = unpack2(ax), a23 = unpack2(ay);
            float4 pv = *(const float4*)&sm.P[t & 3][tid * 4];
            hin.x = tanh_fast(pv.x + a01.x);
            hin.y = tanh_fast(pv.y + a01.y);
            hin.z = tanh_fast(pv.z + a23.x);
            hin.w = tanh_fast(pv.w + a23.y);
            *(float4*)&sm.Hin[m][lane * 4] = hin;
            *(float4*)&sm.VcT[p][m][lane * 4] =
                make_float4(hin.x * dreg.x, hin.y * dreg.y,
                            hin.z * dreg.z, hin.w * dreg.w);
        }
        __syncwarp();

        {
            ull a0 = 0, a1 = 0, a2 = 0, a3 = 0;
            const ulonglong2* hb = (const ulonglong2*)&sm.Hin[m][0];
#pragma unroll
            for (int i = 0; i < 32; i += 2) {
                ulonglong2 h0 = hb[i];
                ulonglong2 h1 = hb[i + 1];
                a0 = ffma2(h0.x, wreg[2 * i], a0);
                a1 = ffma2(h0.y, wreg[2 * i + 1], a1);
                a2 = ffma2(h1.x, wreg[2 * i + 2], a2);
                a3 = ffma2(h1.y, wreg[2 * i + 3], a3);
            }
            ull sB_ = fadd2(fadd2(a0, a1), fadd2(a2, a3));
            float2 sb = unpack2(sB_);
            sm.KQ[p][m][lane] = sb.x + sb.y;
        }
        __syncthreads();

        {
            int mq = lane >> 2, g = lane & 3;
            float L0a = 0.f, L0b = 0.f, L1a = 0.f, L1b = 0.f;
#pragma unroll
            for (int k = 0; k < 16; k += 2) {
                float q0 = sm.KQ[p][mq][16 + k];
                float q1 = sm.KQ[p][mq][16 + k + 1];
                L0a += q0 * sm.KQ[p][2 * g][k];
                L0b += q1 * sm.KQ[p][2 * g][k + 1];
                L1a += q0 * sm.KQ[p][2 * g + 1][k];
                L1b += q1 * sm.KQ[p][2 * g + 1][k + 1];
            }
            float L0 = (L0a + L0b) * 0.25f, L1 = (L1a + L1b) * 0.25f;
            float mx = fmaxf(L0, L1);
            mx = fmaxf(mx, __shfl_xor_sync(0xffffffffu, mx, 1));
            mx = fmaxf(mx, __shfl_xor_sync(0xffffffffu, mx, 2));
            float e0 = __expf(L0 - mx), e1 = __expf(L1 - mx);
            float s = e0 + e1;
            s += __shfl_xor_sync(0xffffffffu, s, 1);
            s += __shfl_xor_sync(0xffffffffu, s, 2);
            float inv = 1.0f / s;
            float a0 = e0 * inv, a1 = e1 * inv;

            if (w == 0)
                *(float2*)&arim[((size_t)t * B_ + b) * 64 + lane * 2] =
                    make_float2(a0, a1);

            int n = w;
            float av = (n & 1) ? a1 : a0;
            ull cx = 0, cy = 0, cx2 = 0, cy2 = 0;
#pragma unroll
            for (int mm = 0; mm < 8; mm += 2) {
                float aa = __shfl_sync(0xffffffffu, av, mm * 4 + (n >> 1));
                float ab = __shfl_sync(0xffffffffu, av, (mm + 1) * 4 + (n >> 1));
                ull apa = pack2(aa, aa), apb = pack2(ab, ab);
                ulonglong2 vc0 = *(const ulonglong2*)&sm.VcT[p][mm][lane * 4];
                ulonglong2 vc1 = *(const ulonglong2*)&sm.VcT[p][mm + 1][lane * 4];
                cx  = ffma2(apa, vc0.x, cx);
                cy  = ffma2(apa, vc0.y, cy);
                cx2 = ffma2(apb, vc1.x, cx2);
                cy2 = ffma2(apb, vc1.y, cy2);
            }
            cx = fadd2(cx, cx2);
            cy = fadd2(cy, cy2);
            float2 c01 = unpack2(cx), c23 = unpack2(cy);
            float4 ac = make_float4(c01.x, c01.y, c23.x, c23.y);
            float4 hn = make_float4(hin.x + ac.x, hin.y + ac.y,
                                    hin.z + ac.z, hin.w + ac.w);
            *(float4*)&sm.Hst[n][lane * 4] = hn;
            size_t base = (((size_t)t * B_ + b) * M_ + n) * H_ + lane * 4;
            *(float4*)&hid[base] = hn;
            *(float4*)&acomm[base] = ac;
        }
        __syncwarp();
    }
}

// ---------------------------------------------------------------------------
// k_out v3: 128x128 tile, BK=16, register-prefetch double buffering, f32x2.
// grid 512, 256 threads.
// ---------------------------------------------------------------------------
__global__ __launch_bounds__(256) void k_out(const float* __restrict__ hid,
        const float* __restrict__ Wo, const float* __restrict__ bo,
        float* __restrict__ outp) {
    __shared__ float sAT[16][132];
    __shared__ float sB[16][132];
    int r0 = blockIdx.x * 128;
    int tid = threadIdx.x;
    int tx = tid & 15, ty = tid >> 4;

    int lrow = tid >> 1;
    int lkq  = (tid & 1) * 8;
    const float* aptr = hid + (size_t)(r0 + lrow) * 1024 + lkq;
    const float* bptr = Wo + (size_t)lrow * 1024 + lkq;

    ull acc[8][4];
#pragma unroll
    for (int a = 0; a < 8; a++)
#pragma unroll
        for (int c = 0; c < 4; c++) acc[a][c] = 0ull;

    float4 ra0 = *(const float4*)aptr;
    float4 ra1 = *(const float4*)(aptr + 4);
    float4 rb0 = *(const float4*)bptr;
    float4 rb1 = *(const float4*)(bptr + 4);

    for (int kc = 0; kc < 1024; kc += 16) {
        sAT[lkq + 0][lrow] = ra0.x; sAT[lkq + 1][lrow] = ra0.y;
        sAT[lkq + 2][lrow] = ra0.z; sAT[lkq + 3][lrow] = ra0.w;
        sAT[lkq + 4][lrow] = ra1.x; sAT[lkq + 5][lrow] = ra1.y;
        sAT[lkq + 6][lrow] = ra1.z; sAT[lkq + 7][lrow] = ra1.w;
        sB[lkq + 0][lrow] = rb0.x; sB[lkq + 1][lrow] = rb0.y;
        sB[lkq + 2][lrow] = rb0.z; sB[lkq + 3][lrow] = rb0.w;
        sB[lkq + 4][lrow] = rb1.x; sB[lkq + 5][lrow] = rb1.y;
        sB[lkq + 6][lrow] = rb1.z; sB[lkq + 7][lrow] = rb1.w;
        __syncthreads();
        if (kc + 16 < 1024) {
            aptr += 16; bptr += 16;
            ra0 = *(const float4*)aptr; ra1 = *(const float4*)(aptr + 4);
            rb0 = *(const float4*)bptr; rb1 = *(const float4*)(bptr + 4);
        }
#pragma unroll
        for (int k = 0; k < 16; k++) {
            float4 av0 = *(const float4*)&sAT[k][ty * 8];
            float4 av1 = *(const float4*)&sAT[k][ty * 8 + 4];
            float4 bv0 = *(const float4*)&sB[k][tx * 4];
            float4 bv1 = *(const float4*)&sB[k][64 + tx * 4];
            ull bb0 = pack2(bv0.x, bv0.y), bb1 = pack2(bv0.z, bv0.w);
            ull bb2 = pack2(bv1.x, bv1.y), bb3 = pack2(bv1.z, bv1.w);
            float av[8] = {av0.x, av0.y, av0.z, av0.w, av1.x, av1.y, av1.z, av1.w};
#pragma unroll
            for (int rr = 0; rr < 8; rr++) {
                ull ap = pack2(av[rr], av[rr]);
                acc[rr][0] = ffma2(ap, bb0, acc[rr][0]);
                acc[rr][1] = ffma2(ap, bb1, acc[rr][1]);
                acc[rr][2] = ffma2(ap, bb2, acc[rr][2]);
                acc[rr][3] = ffma2(ap, bb3, acc[rr][3]);
            }
        }
        __syncthreads();
    }
    float4 b4a = *(const float4*)&bo[tx * 4];
    float4 b4b = *(const float4*)&bo[64 + tx * 4];
#pragma unroll
    for (int rr = 0; rr < 8; rr++) {
        int rg = r0 + ty * 8 + rr;
        int t = rg >> 7, b = rg & 127;
        float2 v0 = unpack2(acc[rr][0]), v1 = unpack2(acc[rr][1]);
        float2 v2 = unpack2(acc[rr][2]), v3 = unpack2(acc[rr][3]);
        float* orow = outp + ((size_t)b * 512 + t) * 128;
        *(float4*)&orow[tx * 4] =
            make_float4(v0.x + b4a.x, v0.y + b4a.y, v1.x + b4a.z, v1.y + b4a.w);
        *(float4*)&orow[64 + tx * 4] =
            make_float4(v2.x + b4b.x, v2.y + b4b.y, v3.x + b4b.z, v3.y + b4b.w);
    }
}

// ---------------------------------------------------------------------------
extern "C" void kernel_launch(void* const* d_in, const int* in_sizes, int n_in,
                              void* d_out, int out_size) {
    const float* x    = (const float*)d_in[0];
    const float* Wp   = (const float*)d_in[1];
    const float* bp   = (const float*)d_in[2];
    const float* U    = (const float*)d_in[3];
    const float* V    = (const float*)d_in[4];
    const float* cb   = (const float*)d_in[5];
    const float* Win  = (const float*)d_in[6];
    const float* WQ   = (const float*)d_in[7];
    const float* WK   = (const float*)d_in[8];
    const float* WV   = (const float*)d_in[9];
    const float* Wo   = (const float*)d_in[10];
    const float* bo   = (const float*)d_in[11];

    float* out = (float*)d_out;
    float* outputs = out + OFF_OUT;
    float* hid     = out + OFF_HID;
    float* ain     = out + OFF_AIN;
    float* acomm   = out + OFF_ACOMM;
    float* arim    = out + OFF_ARIM;

    cudaFuncSetAttribute(k_rnn, cudaFuncAttributeMaxDynamicSharedMemorySize,
                         (int)sizeof(Smem3));
    cudaFuncSetAttribute(k_pre_mma, cudaFuncAttributeMaxDynamicSharedMemorySize,
                         PM_SMEM);

    k_weff<<<dim3(2, 8), 256>>>(Win, Wp);
    k_wcvt<<<dim3(8, 8), 256>>>(Win, bp, cb);
    k_pre_mma<<<1024, 256, PM_SMEM>>>(x, ain);
    k_rnn<<<128, 256, sizeof(Smem3)>>>(U, V, WQ, WK, WV, hid, acomm, arim);
    k_out<<<512, 256>>>(hid, Wo, bo, outputs);
}

// round 16
// speedup vs baseline: 1.3617x; 1.0681x over previous
#include <cuda_runtime.h>
#include <cuda_bf16.h>
#include <cstdint>

#define B_ 128
#define S_ 512
#define I_ 128
#define H_ 128
#define M_ 8
#define KD_ 16
#define R_ 16
#define O_ 128

// output region offsets (floats), concatenated in reference return order
#define OFF_OUT   ((size_t)0)                 // [B,S,O]      8388608
#define OFF_HID   ((size_t)8388608)           // [S,B,M,H]   67108864
#define OFF_AIN   ((size_t)75497472)          // [S,B,M,H]   67108864
#define OFF_ACOMM ((size_t)142606336)         // [S,B,M,H]   67108864
#define OFF_ARIM  ((size_t)209715200)         // [S,B,M,M]    4194304

__device__ float g_P[(size_t)S_ * B_ * M_ * H_];   // precomputed input_part + biases
__device__ float g_Weff[M_ * I_ * H_];             // W_in @ Wp^T per mechanism
// bf16-split weights for k_pre_mma: [m][n(256)][k(128)], n<128 = Win col, n>=128 = Weff col
__device__ __nv_bfloat16 g_Wh[M_ * 256 * 128];
__device__ __nv_bfloat16 g_Wl[M_ * 256 * 128];
__device__ float g_bias[M_ * 128];                 // bp + cb
// bf16-split Wo for k_out_mma: [o(128)][k(1024)] (same layout as Wo itself)
__device__ __nv_bfloat16 g_Woh[O_ * 1024];
__device__ __nv_bfloat16 g_Wol[O_ * 1024];

typedef unsigned long long ull;

__device__ __forceinline__ ull ffma2(ull a, ull b, ull c) {
    ull d;
    asm("fma.rn.f32x2 %0, %1, %2, %3;" : "=l"(d) : "l"(a), "l"(b), "l"(c));
    return d;
}
__device__ __forceinline__ ull fadd2(ull a, ull b) {
    ull d;
    asm("add.rn.f32x2 %0, %1, %2;" : "=l"(d) : "l"(a), "l"(b));
    return d;
}
__device__ __forceinline__ ull pack2(float x, float y) {
    ull d; asm("mov.b64 %0, {%1, %2};" : "=l"(d) : "f"(x), "f"(y)); return d;
}
__device__ __forceinline__ float2 unpack2(ull v) {
    float2 r; asm("mov.b64 {%0, %1}, %2;" : "=f"(r.x), "=f"(r.y) : "l"(v)); return r;
}
__device__ __forceinline__ float tanh_fast(float x) {
    float e = __expf(2.0f * x);
    return 1.0f - 2.0f / (e + 1.0f);
}
__device__ __forceinline__ void cp16(void* s, const void* g) {
    unsigned ds = (unsigned)__cvta_generic_to_shared(s);
    asm volatile("cp.async.cg.shared.global [%0], [%1], 16;" :: "r"(ds), "l"(g));
}
// mma.sync m16n8k16 bf16: D += A * B (D=C in-place)
__device__ __forceinline__ void mma_bf16(float* d, const uint32_t* a,
                                         uint32_t b0, uint32_t b1) {
    asm volatile(
        "mma.sync.aligned.m16n8k16.row.col.f32.bf16.bf16.f32 "
        "{%0,%1,%2,%3}, {%4,%5,%6,%7}, {%8,%9}, {%0,%1,%2,%3};"
        : "+f"(d[0]), "+f"(d[1]), "+f"(d[2]), "+f"(d[3])
        : "r"(a[0]), "r"(a[1]), "r"(a[2]), "r"(a[3]), "r"(b0), "r"(b1));
}

// ---------------------------------------------------------------------------
// k_weff: Weff[m][i][o] = sum_h Win[m][i][h] * Wp[m][o][h].  grid (2,8), 256t
// ---------------------------------------------------------------------------
__global__ void k_weff(const float* __restrict__ Win, const float* __restrict__ Wp) {
    __shared__ float sA[64][36];
    __shared__ float sBt[32][132];
    int m = blockIdx.y;
    int i0 = blockIdx.x * 64;
    int tid = threadIdx.x;
    int ty = tid >> 5, tx = tid & 31;
    int w = tid >> 5, lane = tid & 31;

    float acc[8][4];
#pragma unroll
    for (int a = 0; a < 8; a++)
#pragma unroll
        for (int c = 0; c < 4; c++) acc[a][c] = 0.f;

    const float* A = Win + m * 16384;
    const float* Bm = Wp + m * 16384;

    for (int kc = 0; kc < 128; kc += 32) {
        {
            int row = tid >> 2, cs = (tid & 3) * 8;
            const float* ap = A + (i0 + row) * 128 + kc + cs;
            *(float4*)&sA[row][cs]     = *(const float4*)ap;
            *(float4*)&sA[row][cs + 4] = *(const float4*)(ap + 4);
        }
        {
            int og = lane >> 3, ii0 = (lane & 7) * 4;
#pragma unroll
            for (int it = 0; it < 4; it++) {
                int o = (w << 4) + og + (it << 2);
                float4 v = *(const float4*)(Bm + o * 128 + kc + ii0);
                sBt[ii0 + 0][o] = v.x; sBt[ii0 + 1][o] = v.y;
                sBt[ii0 + 2][o] = v.z; sBt[ii0 + 3][o] = v.w;
            }
        }
        __syncthreads();
#pragma unroll 8
        for (int kk = 0; kk < 32; kk++) {
            float4 wv = *(float4*)&sBt[kk][tx * 4];
#pragma unroll
            for (int rr = 0; rr < 8; rr++) {
                float av = sA[ty * 8 + rr][kk];
                acc[rr][0] += av * wv.x; acc[rr][1] += av * wv.y;
                acc[rr][2] += av * wv.z; acc[rr][3] += av * wv.w;
            }
        }
        __syncthreads();
    }
    float* dst = g_Weff + m * 16384;
#pragma unroll
    for (int rr = 0; rr < 8; rr++) {
        float4 v = make_float4(acc[rr][0], acc[rr][1], acc[rr][2], acc[rr][3]);
        *(float4*)&dst[(i0 + ty * 8 + rr) * 128 + tx * 4] = v;
    }
}

// ---------------------------------------------------------------------------
// k_wcvt: convert [Win^T | Weff^T] to bf16 hi/lo, layout [m][n][k] (k-contig).
// grid (8, 8): x = k-chunk of 16, y = m. 256 threads (thread = n).
// ---------------------------------------------------------------------------
__global__ void k_wcvt(const float* __restrict__ Win, const float* __restrict__ bp,
                       const float* __restrict__ cb) {
    int m = blockIdx.y;
    int kc = blockIdx.x;
    int n = threadIdx.x;
#pragma unroll
    for (int kk = 0; kk < 16; kk++) {
        int k = kc * 16 + kk;
        float v = (n < 128) ? Win[m * 16384 + k * 128 + n]
                            : g_Weff[m * 16384 + k * 128 + (n - 128)];
        __nv_bfloat16 h = __float2bfloat16(v);
        __nv_bfloat16 l = __float2bfloat16(v - __bfloat162float(h));
        size_t o = ((size_t)m * 256 + n) * 128 + k;
        g_Wh[o] = h;
        g_Wl[o] = l;
    }
    if (kc == 0 && n < 128)
        g_bias[m * 128 + n] = bp[m * 128 + n] + cb[m * 128 + n];
}

// ---------------------------------------------------------------------------
// k_wocvt: element-wise split of Wo (already [o][k] k-contig). grid 128, 256t.
// ---------------------------------------------------------------------------
__global__ void k_wocvt(const float* __restrict__ Wo) {
    int i0 = (blockIdx.x * 256 + threadIdx.x) * 4;
#pragma unroll
    for (int j = 0; j < 4; j++) {
        float v = Wo[i0 + j];
        __nv_bfloat16 h = __float2bfloat16(v);
        g_Woh[i0 + j] = h;
        g_Wol[i0 + j] = __float2bfloat16(v - __bfloat162float(h));
    }
}

// ---------------------------------------------------------------------------
// k_pre_mma: HMMA bf16-split GEMM. grid 1024 (64 b-rows x one t), 256 thr.
// ---------------------------------------------------------------------------
#define XH_OFF   0
#define XL_OFF   17408
#define WB_OFF   34816
#define WB_SIZE  73728           // hi 36864 + lo 36864
#define WB_LO    36864
#define PM_SMEM  (34816 + 2 * 73728)

__device__ __forceinline__ void pm_issue_chunk(char* smbase, int c,
        int tid) {
    int m = c >> 1, kh = c & 1;
    char* buf = smbase + WB_OFF + (size_t)(c & 1) * WB_SIZE;
#pragma unroll
    for (int it = 0; it < 2; it++) {
        int i = tid + it * 256;
        int n = i & 255;
        int hi = (i < 256);
        const __nv_bfloat16* src = (hi ? g_Wh : g_Wl)
            + ((size_t)m * 256 + n) * 128 + kh * 64;
        char* dst = buf + (hi ? 0 : WB_LO) + n * 144;
#pragma unroll
        for (int j = 0; j < 8; j++)
            cp16(dst + j * 16, src + j * 8);
    }
    asm volatile("cp.async.commit_group;");
}

__global__ __launch_bounds__(256, 1) void k_pre_mma(const float* __restrict__ x,
        float* __restrict__ ain) {
    extern __shared__ char sm[];
    char* xh = sm + XH_OFF;
    char* xl = sm + XL_OFF;
    int tid = threadIdx.x, wid = tid >> 5, lane = tid & 31;
    int g = lane >> 2, tg = lane & 3;
    int r0 = blockIdx.x * 64;
    int t = r0 >> 7, b0 = r0 & 127;

    // ---- convert x tile (64 rows x 128 k) to bf16 hi/lo smem ----
    {
        int r = tid >> 2, c0 = (tid & 3) * 32;
        const float* xp = x + ((size_t)(b0 + r) * 512 + t) * 128 + c0;
        char* dh = xh + r * 272 + c0 * 2;
        char* dl = xl + r * 272 + c0 * 2;
#pragma unroll
        for (int j = 0; j < 32; j += 4) {
            float4 v = *(const float4*)(xp + j);
            float vv[4] = {v.x, v.y, v.z, v.w};
            union { __nv_bfloat16 b[4]; ull u; } ph, pl;
#pragma unroll
            for (int e = 0; e < 4; e++) {
                ph.b[e] = __float2bfloat16(vv[e]);
                pl.b[e] = __float2bfloat16(vv[e] - __bfloat162float(ph.b[e]));
            }
            *(ull*)(dh + j * 2) = ph.u;
            *(ull*)(dl + j * 2) = pl.u;
        }
    }

    pm_issue_chunk(sm, 0, tid);
    pm_issue_chunk(sm, 1, tid);

    float acc[2][8][4];
#pragma unroll
    for (int a = 0; a < 2; a++)
#pragma unroll
        for (int b = 0; b < 8; b++)
#pragma unroll
            for (int c = 0; c < 4; c++) acc[a][b][c] = 0.f;

    for (int cc = 0; cc < 16; cc++) {
        int m = cc >> 1, kh = cc & 1;
        if (cc < 15) asm volatile("cp.async.wait_group 1;");
        else         asm volatile("cp.async.wait_group 0;");
        __syncthreads();

        const char* wb  = sm + WB_OFF + (size_t)(cc & 1) * WB_SIZE;
        const char* wbl = wb + WB_LO;
#pragma unroll
        for (int ks = 0; ks < 4; ks++) {
            uint32_t aH[2][4], aL[2][4];
#pragma unroll
            for (int ng = 0; ng < 2; ng++) {
                int row = wid * 32 + ng * 16 + g;
                const char* ab = wb + row * 144 + (ks * 16 + tg * 2) * 2;
                aH[ng][0] = *(const uint32_t*)ab;
                aH[ng][1] = *(const uint32_t*)(ab + 8 * 144);
                aH[ng][2] = *(const uint32_t*)(ab + 16);
                aH[ng][3] = *(const uint32_t*)(ab + 8 * 144 + 16);
                const char* al = wbl + row * 144 + (ks * 16 + tg * 2) * 2;
                aL[ng][0] = *(const uint32_t*)al;
                aL[ng][1] = *(const uint32_t*)(al + 8 * 144);
                aL[ng][2] = *(const uint32_t*)(al + 16);
                aL[ng][3] = *(const uint32_t*)(al + 8 * 144 + 16);
            }
#pragma unroll
            for (int rt = 0; rt < 8; rt++) {
                uint32_t boff = (rt * 8 + g) * 272 + (kh * 64 + ks * 16 + tg * 2) * 2;
                uint32_t bh0 = *(const uint32_t*)(xh + boff);
                uint32_t bh1 = *(const uint32_t*)(xh + boff + 16);
                uint32_t bl0 = *(const uint32_t*)(xl + boff);
                uint32_t bl1 = *(const uint32_t*)(xl + boff + 16);
#pragma unroll
                for (int ng = 0; ng < 2; ng++) {
                    mma_bf16(acc[ng][rt], aH[ng], bh0, bh1);
                    mma_bf16(acc[ng][rt], aH[ng], bl0, bl1);
                    mma_bf16(acc[ng][rt], aL[ng], bh0, bh1);
                }
            }
        }

        if (kh) {
#pragma unroll
            for (int ng = 0; ng < 2; ng++) {
                int n = wid * 32 + ng * 16 + g;
                int hcol = (n < 128) ? n : (n - 128);
                float* base = (n < 128) ? ain : g_P;
                float bA = 0.f, bB = 0.f;
                if (n >= 128) {
                    bA = g_bias[m * 128 + hcol];
                    bB = g_bias[m * 128 + hcol + 8];
                }
#pragma unroll
                for (int rt = 0; rt < 8; rt++) {
                    int br = rt * 8 + tg * 2;
                    size_t rb = ((size_t)((t * 128 + b0 + br) * 8 + m)) * 128;
                    base[rb + hcol]              = acc[ng][rt][0] + bA;
                    base[rb + 1024 + hcol]       = acc[ng][rt][1] + bA;
                    base[rb + hcol + 8]          = acc[ng][rt][2] + bB;
                    base[rb + 1024 + hcol + 8]   = acc[ng][rt][3] + bB;
                    acc[ng][rt][0] = 0.f; acc[ng][rt][1] = 0.f;
                    acc[ng][rt][2] = 0.f; acc[ng][rt][3] = 0.f;
                }
            }
        }
        __syncthreads();
        if (cc + 2 < 16) pm_issue_chunk(sm, cc + 2, tid);
    }
}

// ---------------------------------------------------------------------------
// k_out_mma: HMMA bf16-split for out = hid @ Wo^T + bo. grid 1024, 256 thr.
//   Block = 64 (t,b)-rows x 128 out cols; K = 1024 in 16 chunks of 64.
//   Weights cp.async double-buffered; hid fp32 reg-prefetched + converted.
// smem: oxh[64][72]bf16 (144B rows), oxl same; 2 weight buffers, each
//       hi[128][72]bf16 + lo[128][72]bf16.
// ---------------------------------------------------------------------------
#define OX_H     0
#define OX_L     9216
#define OW_OFF   18432
#define OW_SIZE  36864           // hi 18432 + lo 18432
#define OW_LO    18432
#define KO_SMEM  (18432 + 2 * 36864)

__device__ __forceinline__ void ko_issue_chunk(char* smbase, int cc, int tid) {
    char* buf = smbase + OW_OFF + (size_t)(cc & 1) * OW_SIZE;
    int n = tid & 127;
    int hi = (tid < 128);
    const __nv_bfloat16* src = (hi ? g_Woh : g_Wol) + (size_t)n * 1024 + cc * 64;
    char* dst = buf + (hi ? 0 : OW_LO) + n * 144;
#pragma unroll
    for (int j = 0; j < 8; j++)
        cp16(dst + j * 16, src + j * 8);
    asm volatile("cp.async.commit_group;");
}

__global__ __launch_bounds__(256, 1) void k_out_mma(const float* __restrict__ hid,
        const float* __restrict__ bo, float* __restrict__ outp) {
    extern __shared__ char sm[];
    char* xh = sm + OX_H;
    char* xl = sm + OX_L;
    int tid = threadIdx.x, wid = tid >> 5, lane = tid & 31;
    int g = lane >> 2, tg = lane & 3;
    int r0 = blockIdx.x * 64;

    int cr = tid >> 2, cc0 = (tid & 3) * 16;      // conversion coords
    const float* hrow = hid + (size_t)(r0 + cr) * 1024 + cc0;

    // prefetch chunk 0 hid fp32
    float4 rh[4];
#pragma unroll
    for (int j = 0; j < 4; j++) rh[j] = *(const float4*)(hrow + j * 4);

    ko_issue_chunk(sm, 0, tid);
    ko_issue_chunk(sm, 1, tid);

    float acc[8][4];
#pragma unroll
    for (int b = 0; b < 8; b++)
#pragma unroll
        for (int c = 0; c < 4; c++) acc[b][c] = 0.f;

    for (int cc = 0; cc < 16; cc++) {
        // store converted hid chunk (buffer free per bottom barrier)
        {
            char* dh = xh + cr * 144 + cc0 * 2;
            char* dl = xl + cr * 144 + cc0 * 2;
#pragma unroll
            for (int j = 0; j < 4; j++) {
                float vv[4] = {rh[j].x, rh[j].y, rh[j].z, rh[j].w};
                union { __nv_bfloat16 b[4]; ull u; } ph, pl;
#pragma unroll
                for (int e = 0; e < 4; e++) {
                    ph.b[e] = __float2bfloat16(vv[e]);
                    pl.b[e] = __float2bfloat16(vv[e] - __bfloat162float(ph.b[e]));
                }
                *(ull*)(dh + j * 8) = ph.u;
                *(ull*)(dl + j * 8) = pl.u;
            }
        }
        if (cc < 15) asm volatile("cp.async.wait_group 1;");
        else         asm volatile("cp.async.wait_group 0;");
        __syncthreads();

        // prefetch next chunk's hid fp32
        if (cc + 1 < 16) {
            const float* hp = hrow + (cc + 1) * 64;
#pragma unroll
            for (int j = 0; j < 4; j++) rh[j] = *(const float4*)(hp + j * 4);
        }

        const char* wb  = sm + OW_OFF + (size_t)(cc & 1) * OW_SIZE;
        const char* wbl = wb + OW_LO;
#pragma unroll
        for (int ks = 0; ks < 4; ks++) {
            uint32_t aH[4], aL[4];
            {
                int row = wid * 16 + g;
                const char* ab = wb + row * 144 + (ks * 16 + tg * 2) * 2;
                aH[0] = *(const uint32_t*)ab;
                aH[1] = *(const uint32_t*)(ab + 8 * 144);
                aH[2] = *(const uint32_t*)(ab + 16);
                aH[3] = *(const uint32_t*)(ab + 8 * 144 + 16);
                const char* al = wbl + row * 144 + (ks * 16 + tg * 2) * 2;
                aL[0] = *(const uint32_t*)al;
                aL[1] = *(const uint32_t*)(al + 8 * 144);
                aL[2] = *(const uint32_t*)(al + 16);
                aL[3] = *(const uint32_t*)(al + 8 * 144 + 16);
            }
#pragma unroll
            for (int rt = 0; rt < 8; rt++) {
                uint32_t boff = (rt * 8 + g) * 144 + (ks * 16 + tg * 2) * 2;
                uint32_t bh0 = *(const uint32_t*)(xh + boff);
                uint32_t bh1 = *(const uint32_t*)(xh + boff + 16);
                uint32_t bl0 = *(const uint32_t*)(xl + boff);
                uint32_t bl1 = *(const uint32_t*)(xl + boff + 16);
                mma_bf16(acc[rt], aH, bh0, bh1);
                mma_bf16(acc[rt], aH, bl0, bl1);
                mma_bf16(acc[rt], aL, bh0, bh1);
            }
        }
        __syncthreads();
        if (cc + 2 < 16) ko_issue_chunk(sm, cc + 2, tid);
    }

    // ---- epilogue ----
    {
        int n = wid * 16 + g;
        float bA = bo[n], bB = bo[n + 8];
#pragma unroll
        for (int rt = 0; rt < 8; rt++) {
            int gr = r0 + rt * 8 + tg * 2;
            int t = gr >> 7, b = gr & 127;
            float* o0 = outp + ((size_t)b * 512 + t) * 128;
            float* o1 = outp + ((size_t)(b + 1) * 512 + t) * 128;
            o0[n]     = acc[rt][0] + bA;
            o1[n]     = acc[rt][1] + bA;
            o0[n + 8] = acc[rt][2] + bB;
            o1[n + 8] = acc[rt][3] + bB;
        }
    }
}

// ---------------------------------------------------------------------------
// k_rnn v3c (R11): 128 blocks, 256 threads.
// ---------------------------------------------------------------------------
struct Smem3 {
    float4 Ut4[M_][16][32];
    float V[M_][R_][H_];
    float Hst[M_][H_];
    float Hin[M_][H_];
    float VcT[2][M_][H_];
    float P[4][M_ * H_];
    float KQ[2][M_][33];
};

__global__ __launch_bounds__(256) void k_rnn(
        const float* __restrict__ U, const float* __restrict__ V,
        const float* __restrict__ WQ, const float* __restrict__ WK,
        const float* __restrict__ WV,
        float* __restrict__ hid, float* __restrict__ acomm,
        float* __restrict__ arim) {
    extern __shared__ char raw[];
    Smem3& sm = *reinterpret_cast<Smem3*>(raw);
    int tid = threadIdx.x;
    int b = blockIdx.x;
    int w = tid >> 5, lane = tid & 31;
    const int m = w;
    const int r = lane & 15, hf = lane >> 4;

    {
#pragma unroll
        for (int i = 0; i < 16; i++) {
            int hb = hf * 64 + i * 4;
            float4 v;
            v.x = U[((size_t)m * 128 + hb + 0) * 16 + r];
            v.y = U[((size_t)m * 128 + hb + 1) * 16 + r];
            v.z = U[((size_t)m * 128 + hb + 2) * 16 + r];
            v.w = U[((size_t)m * 128 + hb + 3) * 16 + r];
            sm.Ut4[m][i][lane] = v;
        }
    }
    for (int i = tid * 4; i < M_ * R_ * H_; i += 256 * 4)
        *(float4*)((float*)sm.V + i) = *(const float4*)(V + i);
    for (int e = tid; e < M_ * H_; e += 256) {
        int mm = e >> 7, h = e & 127;
        sm.Hst[mm][h] = 0.f;
    }
    float4 dreg;
    {
        int h = lane * 4;
        dreg.x = WV[((size_t)m * H_ + h + 0) * H_ + h + 0];
        dreg.y = WV[((size_t)m * H_ + h + 1) * H_ + h + 1];
        dreg.z = WV[((size_t)m * H_ + h + 2) * H_ + h + 2];
        dreg.w = WV[((size_t)m * H_ + h + 3) * H_ + h + 3];
    }
    ull wreg[64];
    {
        const float* src = (lane < 16) ? (WK + m * H_ * KD_ + lane)
                                       : (WQ + m * H_ * KD_ + (lane - 16));
#pragma unroll
        for (int hp = 0; hp < 64; hp++)
            wreg[hp] = pack2(src[(2 * hp) * KD_], src[(2 * hp + 1) * KD_]);
    }
    const float* Pb = g_P + (size_t)b * 1024;
#pragma unroll
    for (int pt = 0; pt < 3; pt++) {
        cp16(&sm.P[pt][tid * 4], Pb + (size_t)pt * (B_ * 1024) + tid * 4);
        asm volatile("cp.async.commit_group;");
    }
    __syncthreads();

    for (int t = 0; t < S_; t++) {
        const int p = t & 1;
        if (t + 3 < S_)
            cp16(&sm.P[(t + 3) & 3][tid * 4],
                 Pb + (size_t)(t + 3) * (B_ * 1024) + tid * 4);
        asm volatile("cp.async.commit_group;");
        asm volatile("cp.async.wait_group 3;");

        float4 hin;
        {
            const float4* Hc = (const float4*)&sm.Hst[m][hf * 64];
            ull s0 = 0, s1 = 0, s2 = 0, s3 = 0;
#pragma unroll
            for (int i = 0; i < 16; i += 2) {
                float4 u0 = sm.Ut4[m][i][lane];
                float4 h0 = Hc[i];
                float4 u1 = sm.Ut4[m][i + 1][lane];
                float4 h1 = Hc[i + 1];
                s0 = ffma2(pack2(h0.x, h0.y), pack2(u0.x, u0.y), s0);
                s1 = ffma2(pack2(h0.z, h0.w), pack2(u0.z, u0.w), s1);
                s2 = ffma2(pack2(h1.x, h1.y), pack2(u1.x, u1.y), s2);
                s3 = ffma2(pack2(h1.z, h1.w), pack2(u1.z, u1.w), s3);
            }
            ull sA_ = fadd2(fadd2(s0, s1), fadd2(s2, s3));
            float2 tA = unpack2(sA_);
            float partial = tA.x + tA.y;
            partial += __shfl_xor_sync(0xffffffffu, partial, 16);
            ull ax = 0, ay = 0, ax2 = 0, ay2 = 0;
#pragma unroll
            for (int rr = 0; rr < 16; rr += 2) {
                float t0 = __shfl_sync(0xffffffffu, partial, rr);
                float t1 = __shfl_sync(0xffffffffu, partial, rr + 1);
                ull tp0 = pack2(t0, t0), tp1 = pack2(t1, t1);
                ulonglong2 v0 = *(const ulonglong2*)&sm.V[m][rr][lane * 4];
                ulonglong2 v1 = *(const ulonglong2*)&sm.V[m][rr + 1][lane * 4];
                ax  = ffma2(tp0, v0.x, ax);
                ay  = ffma2(tp0, v0.y, ay);
                ax2 = ffma2(tp1, v1.x, ax2);
                ay2 = ffma2(tp1, v1.y, ay2);
            }
            ax = fadd2(ax, ax2);
            ay = fadd2(ay, ay2);
            float2 a01 = unpack2(ax), a23 = unpack2(ay);
            float4 pv = *(const float4*)&sm.P[t & 3][tid * 4];
            hin.x = tanh_fast(pv.x + a01.x);
            hin.y = tanh_fast(pv.y + a01.y);
            hin.z = tanh_fast(pv.z + a23.x);
            hin.w = tanh_fast(pv.w + a23.y);
            *(float4*)&sm.Hin[m][lane * 4] = hin;
            *(float4*)&sm.VcT[p][m][lane * 4] =
                make_float4(hin.x * dreg.x, hin.y * dreg.y,
                            hin.z * dreg.z, hin.w * dreg.w);
        }
        __syncwarp();

        {
            ull a0 = 0, a1 = 0, a2 = 0, a3 = 0;
            const ulonglong2* hb = (const ulonglong2*)&sm.Hin[m][0];
#pragma unroll
            for (int i = 0; i < 32; i += 2) {
                ulonglong2 h0 = hb[i];
                ulonglong2 h1 = hb[i + 1];
                a0 = ffma2(h0.x, wreg[2 * i], a0);
                a1 = ffma2(h0.y, wreg[2 * i + 1], a1);
                a2 = ffma2(h1.x, wreg[2 * i + 2], a2);
                a3 = ffma2(h1.y, wreg[2 * i + 3], a3);
            }
            ull sB_ = fadd2(fadd2(a0, a1), fadd2(a2, a3));
            float2 sb = unpack2(sB_);
            sm.KQ[p][m][lane] = sb.x + sb.y;
        }
        __syncthreads();

        {
            int mq = lane >> 2, g = lane & 3;
            float L0a = 0.f, L0b = 0.f, L1a = 0.f, L1b = 0.f;
#pragma unroll
            for (int k = 0; k < 16; k += 2) {
                float q0 = sm.KQ[p][mq][16 + k];
                float q1 = sm.KQ[p][mq][16 + k + 1];
                L0a += q0 * sm.KQ[p][2 * g][k];
                L0b += q1 * sm.KQ[p][2 * g][k + 1];
                L1a += q0 * sm.KQ[p][2 * g + 1][k];
                L1b += q1 * sm.KQ[p][2 * g + 1][k + 1];
            }
            float L0 = (L0a + L0b) * 0.25f, L1 = (L1a + L1b) * 0.25f;
            float mx = fmaxf(L0, L1);
            mx = fmaxf(mx, __shfl_xor_sync(0xffffffffu, mx, 1));
            mx = fmaxf(mx, __shfl_xor_sync(0xffffffffu, mx, 2));
            float e0 = __expf(L0 - mx), e1 = __expf(L1 - mx);
            float s = e0 + e1;
            s += __shfl_xor_sync(0xffffffffu, s, 1);
            s += __shfl_xor_sync(0xffffffffu, s, 2);
            float inv = 1.0f / s;
            float a0 = e0 * inv, a1 = e1 * inv;

            if (w == 0)
                *(float2*)&arim[((size_t)t * B_ + b) * 64 + lane * 2] =
                    make_float2(a0, a1);

            int n = w;
            float av = (n & 1) ? a1 : a0;
            ull cx = 0, cy = 0, cx2 = 0, cy2 = 0;
#pragma unroll
            for (int mm = 0; mm < 8; mm += 2) {
                float aa = __shfl_sync(0xffffffffu, av, mm * 4 + (n >> 1));
                float ab = __shfl_sync(0xffffffffu, av, (mm + 1) * 4 + (n >> 1));
                ull apa = pack2(aa, aa), apb = pack2(ab, ab);
                ulonglong2 vc0 = *(const ulonglong2*)&sm.VcT[p][mm][lane * 4];
                ulonglong2 vc1 = *(const ulonglong2*)&sm.VcT[p][mm + 1][lane * 4];
                cx  = ffma2(apa, vc0.x, cx);
                cy  = ffma2(apa, vc0.y, cy);
                cx2 = ffma2(apb, vc1.x, cx2);
                cy2 = ffma2(apb, vc1.y, cy2);
            }
            cx = fadd2(cx, cx2);
            cy = fadd2(cy, cy2);
            float2 c01 = unpack2(cx), c23 = unpack2(cy);
            float4 ac = make_float4(c01.x, c01.y, c23.x, c23.y);
            float4 hn = make_float4(hin.x + ac.x, hin.y + ac.y,
                                    hin.z + ac.z, hin.w + ac.w);
            *(float4*)&sm.Hst[n][lane * 4] = hn;
            size_t base = (((size_t)t * B_ + b) * M_ + n) * H_ + lane * 4;
            *(float4*)&hid[base] = hn;
            *(float4*)&acomm[base] = ac;
        }
        __syncwarp();
    }
}

// ---------------------------------------------------------------------------
extern "C" void kernel_launch(void* const* d_in, const int* in_sizes, int n_in,
                              void* d_out, int out_size) {
    const float* x    = (const float*)d_in[0];
    const float* Wp   = (const float*)d_in[1];
    const float* bp   = (const float*)d_in[2];
    const float* U    = (const float*)d_in[3];
    const float* V    = (const float*)d_in[4];
    const float* cb   = (const float*)d_in[5];
    const float* Win  = (const float*)d_in[6];
    const float* WQ   = (const float*)d_in[7];
    const float* WK   = (const float*)d_in[8];
    const float* WV   = (const float*)d_in[9];
    const float* Wo   = (const float*)d_in[10];
    const float* bo   = (const float*)d_in[11];

    float* out = (float*)d_out;
    float* outputs = out + OFF_OUT;
    float* hid     = out + OFF_HID;
    float* ain     = out + OFF_AIN;
    float* acomm   = out + OFF_ACOMM;
    float* arim    = out + OFF_ARIM;

    cudaFuncSetAttribute(k_rnn, cudaFuncAttributeMaxDynamicSharedMemorySize,
                         (int)sizeof(Smem3));
    cudaFuncSetAttribute(k_pre_mma, cudaFuncAttributeMaxDynamicSharedMemorySize,
                         PM_SMEM);
    cudaFuncSetAttribute(k_out_mma, cudaFuncAttributeMaxDynamicSharedMemorySize,
                         KO_SMEM);

    k_weff<<<dim3(2, 8), 256>>>(Win, Wp);
    k_wcvt<<<dim3(8, 8), 256>>>(Win, bp, cb);
    k_wocvt<<<128, 256>>>(Wo);
    k_pre_mma<<<1024, 256, PM_SMEM>>>(x, ain);
    k_rnn<<<128, 256, sizeof(Smem3)>>>(U, V, WQ, WK, WV, hid, acomm, arim);
    k_out_mma<<<1024, 256, KO_SMEM>>>(hid, bo, outputs);
}